// round 1
// baseline (speedup 1.0000x reference)
#include <cuda_runtime.h>
#include <math.h>

// Problem constants
#define DM   1024
#define LSEQ 2048
#define BB   4
#define HH   256   // heads
#define HD   4     // head dim

// ---------------- scratch (device globals; no allocs allowed) ----------------
__device__ float g_kkey [DM * LSEQ];        // key-side conv kernel (1024, 2048)
__device__ float g_kvker[HH * LSEQ];        // value-side conv kernel (256, 2048)
__device__ float g_q [BB * DM * LSEQ];
__device__ float g_k [BB * DM * LSEQ];
__device__ float g_v [BB * DM * LSEQ];
__device__ float g_kc[BB * DM * LSEQ];      // k after long conv + skip
__device__ float g_y [BB * DM * LSEQ];      // gelu(attention output), channel = d2*256 + h

// =============================================================================
// Kernel A: build multi-scale interpolated kernels, unit-normalized per channel
// parts: i=0..5, scale s=[1,1,2,4,8,16], lengths [64,64,128,256,512,1024] -> 2048
// multiplier 2^(5-i)
// =============================================================================
__global__ void build_kernels(const float* __restrict__ src, float* __restrict__ dst, int nch)
{
    const int c   = blockIdx.x;
    const int tid = threadIdx.x;
    float vals[8];
    float ss = 0.f;
    #pragma unroll
    for (int r = 0; r < 8; r++) {
        int j = tid * 8 + r;
        int i, start;
        if      (j <   64) { i = 0; start = 0;    }
        else if (j <  128) { i = 1; start = 64;   }
        else if (j <  256) { i = 2; start = 128;  }
        else if (j <  512) { i = 3; start = 256;  }
        else if (j < 1024) { i = 4; start = 512;  }
        else               { i = 5; start = 1024; }
        int   s    = (i <= 1) ? 1 : (1 << (i - 1));
        float mult = (float)(1 << (5 - i));
        int   jj   = j - start;
        float pos  = ((float)jj + 0.5f) / (float)s - 0.5f;
        pos = fminf(fmaxf(pos, 0.f), 63.f);
        int   lo = (int)floorf(pos);
        int   hi = min(lo + 1, 63);
        float w  = pos - (float)lo;
        const float* row = src + ((size_t)i * nch + c) * 64;
        float v = (row[lo] * (1.f - w) + row[hi] * w) * mult;
        vals[r] = v;
        ss += v * v;
    }
    __shared__ float red[256];
    red[tid] = ss;
    __syncthreads();
    for (int off = 128; off > 0; off >>= 1) {
        if (tid < off) red[tid] += red[tid + off];
        __syncthreads();
    }
    float inv = 1.f / sqrtf(red[0]);
    #pragma unroll
    for (int r = 0; r < 8; r++)
        dst[(size_t)c * LSEQ + tid * 8 + r] = vals[r] * inv;
}

// =============================================================================
// Kernel B/E: SGEMM with bias.  Y[b,o,n] = sum_k W[o,k] * X[b,k,n] + bias[o]
// M = K = 1024, N = 2048.  64x64 tile, K-step 16, 256 threads, 4x4 microtile.
// =============================================================================
__global__ void __launch_bounds__(256)
sgemm_bias(const float* __restrict__ W, const float* __restrict__ bias,
           const float* __restrict__ X, float* __restrict__ Y)
{
    const int b  = blockIdx.z;
    const int n0 = blockIdx.x * 64;
    const int m0 = blockIdx.y * 64;
    __shared__ float Ws[16][64];
    __shared__ float Xs[16][68];
    const int tid = threadIdx.x;
    const int tm = (tid >> 4) << 2;
    const int tn = (tid & 15) << 2;
    const int wr = tid >> 2;
    const int wc = (tid & 3) << 2;
    const int xr = tid >> 4;
    const int xc = (tid & 15) << 2;
    const float* Xb = X + ((size_t)b << 21);   // b * 1024 * 2048
    float acc[4][4];
    #pragma unroll
    for (int i = 0; i < 4; i++)
        #pragma unroll
        for (int j = 0; j < 4; j++) acc[i][j] = 0.f;

    for (int k0 = 0; k0 < 1024; k0 += 16) {
        float4 wv = *(const float4*)&W[(size_t)(m0 + wr) * 1024 + k0 + wc];
        Ws[wc + 0][wr] = wv.x; Ws[wc + 1][wr] = wv.y;
        Ws[wc + 2][wr] = wv.z; Ws[wc + 3][wr] = wv.w;
        float4 xv = *(const float4*)&Xb[(size_t)(k0 + xr) * 2048 + n0 + xc];
        *(float4*)&Xs[xr][xc] = xv;
        __syncthreads();
        #pragma unroll
        for (int kk = 0; kk < 16; kk++) {
            float a0 = Ws[kk][tm + 0], a1 = Ws[kk][tm + 1];
            float a2 = Ws[kk][tm + 2], a3 = Ws[kk][tm + 3];
            float4 bv = *(const float4*)&Xs[kk][tn];
            acc[0][0] += a0 * bv.x; acc[0][1] += a0 * bv.y; acc[0][2] += a0 * bv.z; acc[0][3] += a0 * bv.w;
            acc[1][0] += a1 * bv.x; acc[1][1] += a1 * bv.y; acc[1][2] += a1 * bv.z; acc[1][3] += a1 * bv.w;
            acc[2][0] += a2 * bv.x; acc[2][1] += a2 * bv.y; acc[2][2] += a2 * bv.z; acc[2][3] += a2 * bv.w;
            acc[3][0] += a3 * bv.x; acc[3][1] += a3 * bv.y; acc[3][2] += a3 * bv.z; acc[3][3] += a3 * bv.w;
        }
        __syncthreads();
    }
    #pragma unroll
    for (int i = 0; i < 4; i++) {
        float bs = bias[m0 + tm + i];
        float4 o;
        o.x = acc[i][0] + bs; o.y = acc[i][1] + bs;
        o.z = acc[i][2] + bs; o.w = acc[i][3] + bs;
        *(float4*)&Y[((size_t)b << 21) + (size_t)(m0 + tm + i) * 2048 + n0 + tn] = o;
    }
}

// =============================================================================
// Kernel C: per-channel causal long conv + skip.
// out[b,c,l] = sum_{m<=l} k[b,c,m]*ker[c,l-m] + k[b,c,l]*dkey[c]
// Formulated as y[l] = sum_j ker[j]*x[l-j], x zero-padded in front.
// smem x stored with stride-9 padding (idx + idx>>3) -> conflict-free warp reads.
// Each thread: 8 consecutive l; j processed in chunks of 8 (64 FMA / 23 LDS).
// =============================================================================
__global__ void __launch_bounds__(256)
keyconv_kernel(const float* __restrict__ kk, const float* __restrict__ kker,
               const float* __restrict__ dkey, float* __restrict__ out)
{
    __shared__ float xp[4608];   // padded zero-extended input (logical 4096)
    __shared__ float ks[2048];   // kernel row
    const int c = blockIdx.x, b = blockIdx.y;
    const int tid = threadIdx.x;
    const size_t rowbase = ((size_t)b * DM + c) * LSEQ;

    for (int i = tid; i < 4608; i += 256) xp[i] = 0.f;
    __syncthreads();
    for (int i = tid; i < 2048; i += 256) {
        ks[i] = kker[(size_t)c * LSEQ + i];
        int p = 2048 + i;
        xp[p + (p >> 3)] = kk[rowbase + i];
    }
    __syncthreads();

    const int wid = tid >> 5, lane = tid & 31;
    const int strip = (wid < 4) ? wid : (11 - wid);   // SMSP-balanced strips
    const int l0 = strip * 256 + lane * 8;
    const int jmaxw = strip * 256 + 255;

    float acc[8];
    #pragma unroll
    for (int r = 0; r < 8; r++) acc[r] = 0.f;

    for (int j0 = 0; j0 <= jmaxw; j0 += 8) {
        float kr[8];
        #pragma unroll
        for (int s = 0; s < 8; s++) kr[s] = ks[j0 + s];
        float xv[15];
        #pragma unroll
        for (int t = 0; t < 15; t++) {
            int p = 2048 + l0 - j0 - 7 + t;
            xv[t] = xp[p + (p >> 3)];
        }
        #pragma unroll
        for (int r = 0; r < 8; r++)
            #pragma unroll
            for (int s = 0; s < 8; s++)
                acc[r] += kr[s] * xv[r - s + 7];
    }
    const float dk = dkey[c];
    #pragma unroll
    for (int r = 0; r < 8; r++) {
        int p = 2048 + l0 + r;
        out[rowbase + l0 + r] = acc[r] + xp[p + (p >> 3)] * dk;
    }
}

// =============================================================================
// Kernel D: kernel-weighted linear attention + D skip + exact GELU.
// Per (b,h) block.  y[d2,l] = sum_{m<=l} (q_l . k_m) ker[l-m] v[d2,m]
//                              + D[h] (q_l . k_l) v[d2,l]
// stores gelu(y) at channel c = d2*256 + h.
// smem: k (4x2048), v (4x2048), padded ker (4608 w/ stride-9 padding).
// =============================================================================
__global__ void __launch_bounds__(256)
attn_kernel(const float* __restrict__ gq, const float* __restrict__ gk,
            const float* __restrict__ gv, const float* __restrict__ kerv,
            const float* __restrict__ Dp, float* __restrict__ gy)
{
    extern __shared__ float sm[];
    float* ks = sm;            // 8192
    float* vs = sm + 8192;     // 8192
    float* kp = sm + 16384;    // 4608 (padded, zero-extended both sides)
    const int h = blockIdx.x, b = blockIdx.y;
    const int tid = threadIdx.x;
    const size_t base = ((size_t)b * DM + (size_t)h * HD) * LSEQ;  // 4 contiguous rows

    for (int i = tid; i < 8192; i += 256) { ks[i] = gk[base + i]; vs[i] = gv[base + i]; }
    for (int i = tid; i < 4608; i += 256) kp[i] = 0.f;
    __syncthreads();
    for (int j = tid; j < 2048; j += 256) {
        int p = 2048 + j;
        kp[p + (p >> 3)] = kerv[(size_t)h * LSEQ + j];
    }
    __syncthreads();

    const int wid = tid >> 5, lane = tid & 31;
    const int strip = (wid < 4) ? wid : (11 - wid);
    const int l0 = strip * 256 + lane * 8;
    const int mmax = strip * 256 + 255;

    float qreg[4][8];
    #pragma unroll
    for (int d1 = 0; d1 < 4; d1++)
        #pragma unroll
        for (int r = 0; r < 8; r++)
            qreg[d1][r] = gq[base + (size_t)d1 * LSEQ + l0 + r];

    float acc[4][8];
    #pragma unroll
    for (int d = 0; d < 4; d++)
        #pragma unroll
        for (int r = 0; r < 8; r++) acc[d][r] = 0.f;

    const int pb = 2048 + l0;   // padded-ker base for r=0

    for (int m = 0; m <= mmax; m++) {
        float k0 = ks[m], k1 = ks[2048 + m], k2 = ks[4096 + m], k3 = ks[6144 + m];
        float v0 = vs[m], v1 = vs[2048 + m], v2 = vs[4096 + m], v3 = vs[6144 + m];
        #pragma unroll
        for (int r = 0; r < 8; r++) {
            float s = qreg[0][r] * k0 + qreg[1][r] * k1 + qreg[2][r] * k2 + qreg[3][r] * k3;
            int p = pb + r - m;
            float w = s * kp[p + (p >> 3)];
            acc[0][r] += w * v0;
            acc[1][r] += w * v1;
            acc[2][r] += w * v2;
            acc[3][r] += w * v3;
        }
    }

    // D skip: D[h] * (q_l . k_l) * v[d2,l]
    const float Dh = Dp[h];
    #pragma unroll
    for (int r = 0; r < 8; r++) {
        int l = l0 + r;
        float s = qreg[0][r] * ks[l] + qreg[1][r] * ks[2048 + l]
                + qreg[2][r] * ks[4096 + l] + qreg[3][r] * ks[6144 + l];
        float w = Dh * s;
        acc[0][r] += w * vs[l];
        acc[1][r] += w * vs[2048 + l];
        acc[2][r] += w * vs[4096 + l];
        acc[3][r] += w * vs[6144 + l];
    }

    // exact GELU + store at channel d2*256 + h
    #pragma unroll
    for (int d2 = 0; d2 < 4; d2++) {
        size_t orow = ((size_t)b * DM + (size_t)d2 * HH + h) * LSEQ + l0;
        #pragma unroll
        for (int r = 0; r < 8; r++) {
            float x = acc[d2][r];
            gy[orow + r] = 0.5f * x * (1.f + erff(x * 0.70710678118654752f));
        }
    }
}

// =============================================================================
extern "C" void kernel_launch(void* const* d_in, const int* in_sizes, int n_in,
                              void* d_out, int out_size)
{
    const float* u       = (const float*)d_in[0];
    const float* q_w     = (const float*)d_in[1];
    const float* q_b     = (const float*)d_in[2];
    const float* k_w     = (const float*)d_in[3];
    const float* k_b     = (const float*)d_in[4];
    const float* v_w     = (const float*)d_in[5];
    const float* v_b     = (const float*)d_in[6];
    const float* kkey_in = (const float*)d_in[7];   // (6,1024,64)
    const float* kv_in   = (const float*)d_in[8];   // (6,256,64)
    const float* D_key   = (const float*)d_in[9];   // (1,1024)
    const float* Dh      = (const float*)d_in[10];  // (1,256)
    const float* pw_w    = (const float*)d_in[11];
    const float* pw_b    = (const float*)d_in[12];
    float* out = (float*)d_out;

    float *kkey, *kvk, *q, *k, *v, *kc, *y;
    cudaGetSymbolAddress((void**)&kkey, g_kkey);
    cudaGetSymbolAddress((void**)&kvk,  g_kvker);
    cudaGetSymbolAddress((void**)&q,    g_q);
    cudaGetSymbolAddress((void**)&k,    g_k);
    cudaGetSymbolAddress((void**)&v,    g_v);
    cudaGetSymbolAddress((void**)&kc,   g_kc);
    cudaGetSymbolAddress((void**)&y,    g_y);

    const int ATT_SMEM = (8192 + 8192 + 4608) * (int)sizeof(float);   // 83968 B
    cudaFuncSetAttribute(attn_kernel, cudaFuncAttributeMaxDynamicSharedMemorySize, ATT_SMEM);

    // 1. build conv kernels
    build_kernels<<<DM, 256>>>(kkey_in, kkey, DM);
    build_kernels<<<HH, 256>>>(kv_in,   kvk,  HH);

    // 2. q/k/v projections
    dim3 gg(LSEQ / 64, DM / 64, BB);
    sgemm_bias<<<gg, 256>>>(q_w, q_b, u, q);
    sgemm_bias<<<gg, 256>>>(k_w, k_b, u, k);
    sgemm_bias<<<gg, 256>>>(v_w, v_b, u, v);

    // 3. key-side causal long conv + skip
    keyconv_kernel<<<dim3(DM, BB), 256>>>(k, kkey, D_key, kc);

    // 4. kernel-weighted linear attention + D skip + gelu
    attn_kernel<<<dim3(HH, BB), 256, ATT_SMEM>>>(q, kc, v, kvk, Dh, y);

    // 5. pointwise projection -> out
    sgemm_bias<<<gg, 256>>>(pw_w, pw_b, y, out);
}

// round 3
// speedup vs baseline: 1.5367x; 1.5367x over previous
#include <cuda_runtime.h>
#include <cuda_bf16.h>
#include <stdint.h>
#include <math.h>

// Problem constants
#define DM   1024
#define LSEQ 2048
#define BB   4
#define HH   256   // heads
#define HD   4     // head dim

// ---------------- scratch (device globals; no allocs allowed) ----------------
__device__ float g_kkey [DM * LSEQ];
__device__ float g_kvker[HH * LSEQ];
__device__ float g_q [BB * DM * LSEQ];
__device__ float g_k [BB * DM * LSEQ];
__device__ float g_v [BB * DM * LSEQ];
__device__ float g_kc[BB * DM * LSEQ];
__device__ float g_y [BB * DM * LSEQ];
// bf16 split operands for tensor-core GEMMs
__device__ __nv_bfloat16 g_wh[4][DM * DM];      // q,k,v,pw weight hi
__device__ __nv_bfloat16 g_wl[4][DM * DM];      // lo
__device__ __nv_bfloat16 g_xh[BB * LSEQ * DM];  // transposed activation hi
__device__ __nv_bfloat16 g_xl[BB * LSEQ * DM];  // lo

// ======================= helpers (baseline ISA only) =========================
__device__ __forceinline__ uint32_t smem_u32(const void* p) {
    uint32_t a;
    asm("{ .reg .u64 t; cvta.to.shared.u64 t, %1; cvt.u32.u64 %0, t; }" : "=r"(a) : "l"(p));
    return a;
}
__device__ __forceinline__ void cp16(uint32_t dst, const void* src) {
    asm volatile("cp.async.cg.shared.global [%0], [%1], 16;" :: "r"(dst), "l"(src));
}
__device__ __forceinline__ void ldsm4(uint32_t* r, uint32_t addr) {
    asm volatile("ldmatrix.sync.aligned.m8n8.x4.shared.b16 {%0,%1,%2,%3}, [%4];"
        : "=r"(r[0]), "=r"(r[1]), "=r"(r[2]), "=r"(r[3]) : "r"(addr));
}
__device__ __forceinline__ void mma16816(float* d, const uint32_t* a, const uint32_t* b) {
    asm volatile("mma.sync.aligned.m16n8k16.row.col.f32.bf16.bf16.f32 "
        "{%0,%1,%2,%3}, {%4,%5,%6,%7}, {%8,%9}, {%0,%1,%2,%3};"
        : "+f"(d[0]), "+f"(d[1]), "+f"(d[2]), "+f"(d[3])
        : "r"(a[0]), "r"(a[1]), "r"(a[2]), "r"(a[3]), "r"(b[0]), "r"(b[1]));
}

// =============================================================================
// Kernel A: build multi-scale interpolated kernels (unchanged)
// =============================================================================
__global__ void build_kernels(const float* __restrict__ src, float* __restrict__ dst, int nch)
{
    const int c   = blockIdx.x;
    const int tid = threadIdx.x;
    float vals[8];
    float ss = 0.f;
    #pragma unroll
    for (int r = 0; r < 8; r++) {
        int j = tid * 8 + r;
        int i, start;
        if      (j <   64) { i = 0; start = 0;    }
        else if (j <  128) { i = 1; start = 64;   }
        else if (j <  256) { i = 2; start = 128;  }
        else if (j <  512) { i = 3; start = 256;  }
        else if (j < 1024) { i = 4; start = 512;  }
        else               { i = 5; start = 1024; }
        int   s    = (i <= 1) ? 1 : (1 << (i - 1));
        float mult = (float)(1 << (5 - i));
        int   jj   = j - start;
        float pos  = ((float)jj + 0.5f) / (float)s - 0.5f;
        pos = fminf(fmaxf(pos, 0.f), 63.f);
        int   lo = (int)floorf(pos);
        int   hi = min(lo + 1, 63);
        float w  = pos - (float)lo;
        const float* row = src + ((size_t)i * nch + c) * 64;
        float v = (row[lo] * (1.f - w) + row[hi] * w) * mult;
        vals[r] = v;
        ss += v * v;
    }
    __shared__ float red[256];
    red[tid] = ss;
    __syncthreads();
    for (int off = 128; off > 0; off >>= 1) {
        if (tid < off) red[tid] += red[tid + off];
        __syncthreads();
    }
    float inv = 1.f / sqrtf(red[0]);
    #pragma unroll
    for (int r = 0; r < 8; r++)
        dst[(size_t)c * LSEQ + tid * 8 + r] = vals[r] * inv;
}

// =============================================================================
// bf16 hi/lo split of a weight matrix
// =============================================================================
__global__ void wsplit(const float* __restrict__ w, __nv_bfloat16* __restrict__ h,
                       __nv_bfloat16* __restrict__ l, int n)
{
    int i = blockIdx.x * 256 + threadIdx.x;
    if (i < n) {
        float x = w[i];
        __nv_bfloat16 hh = __float2bfloat16(x);
        h[i] = hh;
        l[i] = __float2bfloat16(x - __bfloat162float(hh));
    }
}

// =============================================================================
// transpose (b, C, L) fp32 -> (b, L, C) bf16 hi/lo
// =============================================================================
__global__ void __launch_bounds__(256)
trans_split(const float* __restrict__ in, __nv_bfloat16* __restrict__ oh,
            __nv_bfloat16* __restrict__ ol)
{
    __shared__ float t[32][33];
    const int tx = threadIdx.x & 31, ty = threadIdx.x >> 5;
    const int l0 = blockIdx.x * 32, c0 = blockIdx.y * 32, b = blockIdx.z;
    #pragma unroll
    for (int i = 0; i < 4; i++) {
        int c = c0 + ty + i * 8;
        t[ty + i * 8][tx] = in[((size_t)b * DM + c) * LSEQ + l0 + tx];
    }
    __syncthreads();
    #pragma unroll
    for (int i = 0; i < 4; i++) {
        int l = l0 + ty + i * 8;
        float x = t[tx][ty + i * 8];
        __nv_bfloat16 h = __float2bfloat16(x);
        __nv_bfloat16 lo = __float2bfloat16(x - __bfloat162float(h));
        size_t o = ((size_t)b * LSEQ + l) * DM + c0 + tx;
        oh[o] = h; ol[o] = lo;
    }
}

// =============================================================================
// mma.sync bf16 split GEMM.  Y[b,o,n] = sum_k W[o,k] X[b,k,n] + bias[o]
// A = W[M,K] K-major, B = X^T[N,K] K-major.  Both in bf16 hi/lo.
// CTA: 256 thr, tile 128(M)x128(N), K-stage 64, 2-stage cp.async ring.
// smem per stage: Ah,Al,Bh,Bl 16KB each = 64KB.  SW128 xor swizzle.
// Warp grid 4(M)x2(N): warp tile 32x64.  3 MMAs per product (drop lo*lo).
// =============================================================================
#define GSTG 65536

__device__ __forceinline__ void g_load_stage(
    uint32_t sbuf, int stage, int tid,
    const char* Wh, const char* Wl, const char* Xh, const char* Xl,
    size_t wrow0, size_t xrow0)
{
    const int k0b = stage * 128;          // 64 bf16 = 128 B
    const int c16 = (tid & 7) * 16;
    const int r0  = tid >> 3;             // 0..31
    #pragma unroll
    for (int t = 0; t < 4; t++) {
        const char* base = (t == 0) ? Wh : (t == 1) ? Wl : (t == 2) ? Xh : Xl;
        const size_t rowbase = (t < 2) ? wrow0 : xrow0;
        #pragma unroll
        for (int j = 0; j < 4; j++) {
            int row = r0 + j * 32;
            int off = row * 128 + c16;
            int sw  = off ^ ((off >> 3) & 0x70);
            cp16(sbuf + t * 16384 + (uint32_t)sw,
                 base + rowbase + (size_t)row * 2048 + k0b + c16);
        }
    }
    asm volatile("cp.async.commit_group;" ::: "memory");
}

__device__ __forceinline__ void g_compute_stage(
    uint32_t sbuf, int lane, int warpM, int warpN, float acc[2][8][4])
{
    const uint32_t Ah = sbuf, Al = sbuf + 16384;
    const uint32_t Bh = sbuf + 32768, Bl = sbuf + 49152;
    #pragma unroll
    for (int kk = 0; kk < 4; kk++) {
        uint32_t ah[2][4], al[2][4], bh[8][2], bl[8][2];
        #pragma unroll
        for (int mt = 0; mt < 2; mt++) {
            int m  = warpM * 32 + mt * 16 + (lane & 15);
            int kb = (kk * 16 + (lane >> 4) * 8) * 2;
            int off = m * 128 + kb;
            int sw  = off ^ ((off >> 3) & 0x70);
            ldsm4(ah[mt], Ah + sw);
            ldsm4(al[mt], Al + sw);
        }
        #pragma unroll
        for (int nb2 = 0; nb2 < 4; nb2++) {
            int n  = warpN * 64 + nb2 * 16 + (lane >> 4) * 8 + (lane & 7);
            int kb = (kk * 16 + ((lane >> 3) & 1) * 8) * 2;
            int off = n * 128 + kb;
            int sw  = off ^ ((off >> 3) & 0x70);
            uint32_t r[4];
            ldsm4(r, Bh + sw);
            bh[nb2 * 2][0] = r[0]; bh[nb2 * 2][1] = r[1];
            bh[nb2 * 2 + 1][0] = r[2]; bh[nb2 * 2 + 1][1] = r[3];
            ldsm4(r, Bl + sw);
            bl[nb2 * 2][0] = r[0]; bl[nb2 * 2][1] = r[1];
            bl[nb2 * 2 + 1][0] = r[2]; bl[nb2 * 2 + 1][1] = r[3];
        }
        #pragma unroll
        for (int mt = 0; mt < 2; mt++)
            #pragma unroll
            for (int nb = 0; nb < 8; nb++) {
                mma16816(acc[mt][nb], ah[mt], bh[nb]);
                mma16816(acc[mt][nb], ah[mt], bl[nb]);
                mma16816(acc[mt][nb], al[mt], bh[nb]);
            }
    }
}

__global__ void __launch_bounds__(256, 1)
mma_gemm(const __nv_bfloat16* __restrict__ Wh, const __nv_bfloat16* __restrict__ Wl,
         const __nv_bfloat16* __restrict__ Xh, const __nv_bfloat16* __restrict__ Xl,
         const float* __restrict__ bias, float* __restrict__ Y)
{
    extern __shared__ char smem[];
    const uint32_t sb = smem_u32(smem);
    const int tid = threadIdx.x, wid = tid >> 5, lane = tid & 31;
    const int warpM = wid & 3, warpN = wid >> 2;
    const int n0 = blockIdx.x * 128, m0 = blockIdx.y * 128, b = blockIdx.z;
    const size_t wrow0 = (size_t)m0 * 2048;                    // bytes
    const size_t xrow0 = ((size_t)b * LSEQ + n0) * 2048;       // bytes

    float acc[2][8][4];
    #pragma unroll
    for (int mt = 0; mt < 2; mt++)
        #pragma unroll
        for (int nb = 0; nb < 8; nb++)
            #pragma unroll
            for (int j = 0; j < 4; j++) acc[mt][nb][j] = 0.f;

    g_load_stage(sb,        0, tid, (const char*)Wh, (const char*)Wl,
                 (const char*)Xh, (const char*)Xl, wrow0, xrow0);
    g_load_stage(sb + GSTG, 1, tid, (const char*)Wh, (const char*)Wl,
                 (const char*)Xh, (const char*)Xl, wrow0, xrow0);

    for (int st = 0; st < 16; st++) {
        if (st < 15) asm volatile("cp.async.wait_group 1;" ::: "memory");
        else         asm volatile("cp.async.wait_group 0;" ::: "memory");
        __syncthreads();
        g_compute_stage(sb + (st & 1) * GSTG, lane, warpM, warpN, acc);
        __syncthreads();
        if (st + 2 < 16)
            g_load_stage(sb + (st & 1) * GSTG, st + 2, tid,
                         (const char*)Wh, (const char*)Wl,
                         (const char*)Xh, (const char*)Xl, wrow0, xrow0);
    }

    // epilogue: direct register -> gmem, bias fused
    const int rq = lane >> 2;          // 0..7
    const int cq = (lane & 3) * 2;
    #pragma unroll
    for (int mt = 0; mt < 2; mt++) {
        const int r0 = m0 + warpM * 32 + mt * 16 + rq;
        const float b0 = bias[r0], b1 = bias[r0 + 8];
        const size_t y0 = ((size_t)b * DM + r0) * LSEQ;
        #pragma unroll
        for (int nb = 0; nb < 8; nb++) {
            const int col = n0 + warpN * 64 + nb * 8 + cq;
            float2 v0, v1;
            v0.x = acc[mt][nb][0] + b0; v0.y = acc[mt][nb][1] + b0;
            v1.x = acc[mt][nb][2] + b1; v1.y = acc[mt][nb][3] + b1;
            *(float2*)&Y[y0 + col] = v0;
            *(float2*)&Y[y0 + 8 * LSEQ + col] = v1;
        }
    }
}

// =============================================================================
// Kernel C: per-channel causal long conv + skip (unchanged)
// =============================================================================
__global__ void __launch_bounds__(256)
keyconv_kernel(const float* __restrict__ kk, const float* __restrict__ kker,
               const float* __restrict__ dkey, float* __restrict__ out)
{
    __shared__ float xp[4608];
    __shared__ float ks[2048];
    const int c = blockIdx.x, b = blockIdx.y;
    const int tid = threadIdx.x;
    const size_t rowbase = ((size_t)b * DM + c) * LSEQ;

    for (int i = tid; i < 4608; i += 256) xp[i] = 0.f;
    __syncthreads();
    for (int i = tid; i < 2048; i += 256) {
        ks[i] = kker[(size_t)c * LSEQ + i];
        int p = 2048 + i;
        xp[p + (p >> 3)] = kk[rowbase + i];
    }
    __syncthreads();

    const int wid = tid >> 5, lane = tid & 31;
    const int strip = (wid < 4) ? wid : (11 - wid);
    const int l0 = strip * 256 + lane * 8;
    const int jmaxw = strip * 256 + 255;

    float acc[8];
    #pragma unroll
    for (int r = 0; r < 8; r++) acc[r] = 0.f;

    for (int j0 = 0; j0 <= jmaxw; j0 += 8) {
        float kr[8];
        #pragma unroll
        for (int s = 0; s < 8; s++) kr[s] = ks[j0 + s];
        float xv[15];
        #pragma unroll
        for (int t = 0; t < 15; t++) {
            int p = 2048 + l0 - j0 - 7 + t;
            xv[t] = xp[p + (p >> 3)];
        }
        #pragma unroll
        for (int r = 0; r < 8; r++)
            #pragma unroll
            for (int s = 0; s < 8; s++)
                acc[r] += kr[s] * xv[r - s + 7];
    }
    const float dk = dkey[c];
    #pragma unroll
    for (int r = 0; r < 8; r++) {
        int p = 2048 + l0 + r;
        out[rowbase + l0 + r] = acc[r] + xp[p + (p >> 3)] * dk;
    }
}

// =============================================================================
// Kernel D: kernel-weighted linear attention + D skip + exact GELU (unchanged)
// =============================================================================
__global__ void __launch_bounds__(256)
attn_kernel(const float* __restrict__ gq, const float* __restrict__ gk,
            const float* __restrict__ gv, const float* __restrict__ kerv,
            const float* __restrict__ Dp, float* __restrict__ gy)
{
    extern __shared__ float sm[];
    float* ks = sm;
    float* vs = sm + 8192;
    float* kp = sm + 16384;
    const int h = blockIdx.x, b = blockIdx.y;
    const int tid = threadIdx.x;
    const size_t base = ((size_t)b * DM + (size_t)h * HD) * LSEQ;

    for (int i = tid; i < 8192; i += 256) { ks[i] = gk[base + i]; vs[i] = gv[base + i]; }
    for (int i = tid; i < 4608; i += 256) kp[i] = 0.f;
    __syncthreads();
    for (int j = tid; j < 2048; j += 256) {
        int p = 2048 + j;
        kp[p + (p >> 3)] = kerv[(size_t)h * LSEQ + j];
    }
    __syncthreads();

    const int wid = tid >> 5, lane = tid & 31;
    const int strip = (wid < 4) ? wid : (11 - wid);
    const int l0 = strip * 256 + lane * 8;
    const int mmax = strip * 256 + 255;

    float qreg[4][8];
    #pragma unroll
    for (int d1 = 0; d1 < 4; d1++)
        #pragma unroll
        for (int r = 0; r < 8; r++)
            qreg[d1][r] = gq[base + (size_t)d1 * LSEQ + l0 + r];

    float acc[4][8];
    #pragma unroll
    for (int d = 0; d < 4; d++)
        #pragma unroll
        for (int r = 0; r < 8; r++) acc[d][r] = 0.f;

    const int pb = 2048 + l0;

    for (int m = 0; m <= mmax; m++) {
        float k0 = ks[m], k1 = ks[2048 + m], k2 = ks[4096 + m], k3 = ks[6144 + m];
        float v0 = vs[m], v1 = vs[2048 + m], v2 = vs[4096 + m], v3 = vs[6144 + m];
        #pragma unroll
        for (int r = 0; r < 8; r++) {
            float s = qreg[0][r] * k0 + qreg[1][r] * k1 + qreg[2][r] * k2 + qreg[3][r] * k3;
            int p = pb + r - m;
            float w = s * kp[p + (p >> 3)];
            acc[0][r] += w * v0;
            acc[1][r] += w * v1;
            acc[2][r] += w * v2;
            acc[3][r] += w * v3;
        }
    }

    const float Dh = Dp[h];
    #pragma unroll
    for (int r = 0; r < 8; r++) {
        int l = l0 + r;
        float s = qreg[0][r] * ks[l] + qreg[1][r] * ks[2048 + l]
                + qreg[2][r] * ks[4096 + l] + qreg[3][r] * ks[6144 + l];
        float w = Dh * s;
        acc[0][r] += w * vs[l];
        acc[1][r] += w * vs[2048 + l];
        acc[2][r] += w * vs[4096 + l];
        acc[3][r] += w * vs[6144 + l];
    }

    #pragma unroll
    for (int d2 = 0; d2 < 4; d2++) {
        size_t orow = ((size_t)b * DM + (size_t)d2 * HH + h) * LSEQ + l0;
        #pragma unroll
        for (int r = 0; r < 8; r++) {
            float x = acc[d2][r];
            gy[orow + r] = 0.5f * x * (1.f + erff(x * 0.70710678118654752f));
        }
    }
}

// =============================================================================
extern "C" void kernel_launch(void* const* d_in, const int* in_sizes, int n_in,
                              void* d_out, int out_size)
{
    const float* u       = (const float*)d_in[0];
    const float* q_w     = (const float*)d_in[1];
    const float* q_b     = (const float*)d_in[2];
    const float* k_w     = (const float*)d_in[3];
    const float* k_b     = (const float*)d_in[4];
    const float* v_w     = (const float*)d_in[5];
    const float* v_b     = (const float*)d_in[6];
    const float* kkey_in = (const float*)d_in[7];
    const float* kv_in   = (const float*)d_in[8];
    const float* D_key   = (const float*)d_in[9];
    const float* Dh      = (const float*)d_in[10];
    const float* pw_w    = (const float*)d_in[11];
    const float* pw_b    = (const float*)d_in[12];
    float* out = (float*)d_out;

    float *kkey, *kvk, *q, *k, *v, *kc, *y;
    __nv_bfloat16 *wh, *wl, *xh, *xl;
    cudaGetSymbolAddress((void**)&kkey, g_kkey);
    cudaGetSymbolAddress((void**)&kvk,  g_kvker);
    cudaGetSymbolAddress((void**)&q,    g_q);
    cudaGetSymbolAddress((void**)&k,    g_k);
    cudaGetSymbolAddress((void**)&v,    g_v);
    cudaGetSymbolAddress((void**)&kc,   g_kc);
    cudaGetSymbolAddress((void**)&y,    g_y);
    cudaGetSymbolAddress((void**)&wh,   g_wh);
    cudaGetSymbolAddress((void**)&wl,   g_wl);
    cudaGetSymbolAddress((void**)&xh,   g_xh);
    cudaGetSymbolAddress((void**)&xl,   g_xl);

    const int ATT_SMEM = (8192 + 8192 + 4608) * (int)sizeof(float);
    cudaFuncSetAttribute(attn_kernel, cudaFuncAttributeMaxDynamicSharedMemorySize, ATT_SMEM);
    cudaFuncSetAttribute(mma_gemm, cudaFuncAttributeMaxDynamicSharedMemorySize, 2 * GSTG);

    // 1. build conv kernels
    build_kernels<<<DM, 256>>>(kkey_in, kkey, DM);
    build_kernels<<<HH, 256>>>(kv_in,   kvk,  HH);

    // 2. split weights to bf16 hi/lo
    const int WN = DM * DM;
    wsplit<<<WN / 256, 256>>>(q_w,  wh + 0 * (size_t)WN, wl + 0 * (size_t)WN, WN);
    wsplit<<<WN / 256, 256>>>(k_w,  wh + 1 * (size_t)WN, wl + 1 * (size_t)WN, WN);
    wsplit<<<WN / 256, 256>>>(v_w,  wh + 2 * (size_t)WN, wl + 2 * (size_t)WN, WN);
    wsplit<<<WN / 256, 256>>>(pw_w, wh + 3 * (size_t)WN, wl + 3 * (size_t)WN, WN);

    // 3. transpose + split u -> (b, l, c) bf16
    trans_split<<<dim3(LSEQ / 32, DM / 32, BB), 256>>>(u, xh, xl);

    // 4. q/k/v projections on tensor cores (mma.sync)
    dim3 gg(LSEQ / 128, DM / 128, BB);
    mma_gemm<<<gg, 256, 2 * GSTG>>>(wh + 0 * (size_t)WN, wl + 0 * (size_t)WN, xh, xl, q_b, q);
    mma_gemm<<<gg, 256, 2 * GSTG>>>(wh + 1 * (size_t)WN, wl + 1 * (size_t)WN, xh, xl, k_b, k);
    mma_gemm<<<gg, 256, 2 * GSTG>>>(wh + 2 * (size_t)WN, wl + 2 * (size_t)WN, xh, xl, v_b, v);

    // 5. key-side causal long conv + skip
    keyconv_kernel<<<dim3(DM, BB), 256>>>(k, kkey, D_key, kc);

    // 6. kernel-weighted linear attention + D skip + gelu
    attn_kernel<<<dim3(HH, BB), 256, ATT_SMEM>>>(q, kc, v, kvk, Dh, y);

    // 7. transpose + split y, pointwise projection -> out
    trans_split<<<dim3(LSEQ / 32, DM / 32, BB), 256>>>(y, xh, xl);
    mma_gemm<<<gg, 256, 2 * GSTG>>>(wh + 3 * (size_t)WN, wl + 3 * (size_t)WN, xh, xl, pw_b, out);
}

// round 4
// speedup vs baseline: 1.8084x; 1.1768x over previous
#include <cuda_runtime.h>
#include <cuda_bf16.h>
#include <stdint.h>
#include <math.h>

// Problem constants
#define DM   1024
#define LSEQ 2048
#define BB   4
#define HH   256   // heads
#define HD   4     // head dim

typedef unsigned long long ull;

// ---------------- scratch (device globals; no allocs allowed) ----------------
__device__ float g_kkey [DM * LSEQ];
__device__ float g_kvker[HH * LSEQ];
__device__ float g_q [BB * DM * LSEQ];
__device__ float g_k [BB * DM * LSEQ];
__device__ float g_v [BB * DM * LSEQ];
__device__ float g_kc[BB * DM * LSEQ];
__device__ float g_y [BB * DM * LSEQ];
// bf16 split operands for tensor-core GEMMs
__device__ __nv_bfloat16 g_wh[4][DM * DM];
__device__ __nv_bfloat16 g_wl[4][DM * DM];
__device__ __nv_bfloat16 g_xh[BB * LSEQ * DM];
__device__ __nv_bfloat16 g_xl[BB * LSEQ * DM];

// ======================= helpers (baseline ISA only) =========================
__device__ __forceinline__ uint32_t smem_u32(const void* p) {
    uint32_t a;
    asm("{ .reg .u64 t; cvta.to.shared.u64 t, %1; cvt.u32.u64 %0, t; }" : "=r"(a) : "l"(p));
    return a;
}
__device__ __forceinline__ void cp16(uint32_t dst, const void* src) {
    asm volatile("cp.async.cg.shared.global [%0], [%1], 16;" :: "r"(dst), "l"(src));
}
__device__ __forceinline__ void ldsm4(uint32_t* r, uint32_t addr) {
    asm volatile("ldmatrix.sync.aligned.m8n8.x4.shared.b16 {%0,%1,%2,%3}, [%4];"
        : "=r"(r[0]), "=r"(r[1]), "=r"(r[2]), "=r"(r[3]) : "r"(addr));
}
__device__ __forceinline__ void mma16816(float* d, const uint32_t* a, const uint32_t* b) {
    asm volatile("mma.sync.aligned.m16n8k16.row.col.f32.bf16.bf16.f32 "
        "{%0,%1,%2,%3}, {%4,%5,%6,%7}, {%8,%9}, {%0,%1,%2,%3};"
        : "+f"(d[0]), "+f"(d[1]), "+f"(d[2]), "+f"(d[3])
        : "r"(a[0]), "r"(a[1]), "r"(a[2]), "r"(a[3]), "r"(b[0]), "r"(b[1]));
}
// ---------------- packed fp32x2 (Blackwell) ----------------
__device__ __forceinline__ ull pk2(float a, float b) {
    ull d; asm("mov.b64 %0, {%1, %2};" : "=l"(d) : "f"(a), "f"(b)); return d;
}
__device__ __forceinline__ ull mul2(ull a, ull b) {
    ull d; asm("mul.rn.f32x2 %0, %1, %2;" : "=l"(d) : "l"(a), "l"(b)); return d;
}
__device__ __forceinline__ ull fma2(ull a, ull b, ull c) {
    ull d; asm("fma.rn.f32x2 %0, %1, %2, %3;" : "=l"(d) : "l"(a), "l"(b), "l"(c)); return d;
}
__device__ __forceinline__ void upk2(ull v, float& a, float& b) {
    asm("mov.b64 {%0, %1}, %2;" : "=f"(a), "=f"(b) : "l"(v));
}

// =============================================================================
// Kernel A: build multi-scale interpolated kernels (unchanged)
// =============================================================================
__global__ void build_kernels(const float* __restrict__ src, float* __restrict__ dst, int nch)
{
    const int c   = blockIdx.x;
    const int tid = threadIdx.x;
    float vals[8];
    float ss = 0.f;
    #pragma unroll
    for (int r = 0; r < 8; r++) {
        int j = tid * 8 + r;
        int i, start;
        if      (j <   64) { i = 0; start = 0;    }
        else if (j <  128) { i = 1; start = 64;   }
        else if (j <  256) { i = 2; start = 128;  }
        else if (j <  512) { i = 3; start = 256;  }
        else if (j < 1024) { i = 4; start = 512;  }
        else               { i = 5; start = 1024; }
        int   s    = (i <= 1) ? 1 : (1 << (i - 1));
        float mult = (float)(1 << (5 - i));
        int   jj   = j - start;
        float pos  = ((float)jj + 0.5f) / (float)s - 0.5f;
        pos = fminf(fmaxf(pos, 0.f), 63.f);
        int   lo = (int)floorf(pos);
        int   hi = min(lo + 1, 63);
        float w  = pos - (float)lo;
        const float* row = src + ((size_t)i * nch + c) * 64;
        float v = (row[lo] * (1.f - w) + row[hi] * w) * mult;
        vals[r] = v;
        ss += v * v;
    }
    __shared__ float red[256];
    red[tid] = ss;
    __syncthreads();
    for (int off = 128; off > 0; off >>= 1) {
        if (tid < off) red[tid] += red[tid + off];
        __syncthreads();
    }
    float inv = 1.f / sqrtf(red[0]);
    #pragma unroll
    for (int r = 0; r < 8; r++)
        dst[(size_t)c * LSEQ + tid * 8 + r] = vals[r] * inv;
}

// =============================================================================
// bf16 hi/lo split of a weight matrix
// =============================================================================
__global__ void wsplit(const float* __restrict__ w, __nv_bfloat16* __restrict__ h,
                       __nv_bfloat16* __restrict__ l, int n)
{
    int i = blockIdx.x * 256 + threadIdx.x;
    if (i < n) {
        float x = w[i];
        __nv_bfloat16 hh = __float2bfloat16(x);
        h[i] = hh;
        l[i] = __float2bfloat16(x - __bfloat162float(hh));
    }
}

// =============================================================================
// transpose (b, C, L) fp32 -> (b, L, C) bf16 hi/lo
// =============================================================================
__global__ void __launch_bounds__(256)
trans_split(const float* __restrict__ in, __nv_bfloat16* __restrict__ oh,
            __nv_bfloat16* __restrict__ ol)
{
    __shared__ float t[32][33];
    const int tx = threadIdx.x & 31, ty = threadIdx.x >> 5;
    const int l0 = blockIdx.x * 32, c0 = blockIdx.y * 32, b = blockIdx.z;
    #pragma unroll
    for (int i = 0; i < 4; i++) {
        int c = c0 + ty + i * 8;
        t[ty + i * 8][tx] = in[((size_t)b * DM + c) * LSEQ + l0 + tx];
    }
    __syncthreads();
    #pragma unroll
    for (int i = 0; i < 4; i++) {
        int l = l0 + ty + i * 8;
        float x = t[tx][ty + i * 8];
        __nv_bfloat16 h = __float2bfloat16(x);
        __nv_bfloat16 lo = __float2bfloat16(x - __bfloat162float(h));
        size_t o = ((size_t)b * LSEQ + l) * DM + c0 + tx;
        oh[o] = h; ol[o] = lo;
    }
}

// =============================================================================
// mma.sync bf16 split GEMM, 3-stage cp.async pipeline (192KB smem)
// =============================================================================
#define GSTG 65536

__device__ __forceinline__ void g_load_stage(
    uint32_t sbuf, int stage, int tid,
    const char* Wh, const char* Wl, const char* Xh, const char* Xl,
    size_t wrow0, size_t xrow0)
{
    const int k0b = stage * 128;
    const int c16 = (tid & 7) * 16;
    const int r0  = tid >> 3;
    #pragma unroll
    for (int t = 0; t < 4; t++) {
        const char* base = (t == 0) ? Wh : (t == 1) ? Wl : (t == 2) ? Xh : Xl;
        const size_t rowbase = (t < 2) ? wrow0 : xrow0;
        #pragma unroll
        for (int j = 0; j < 4; j++) {
            int row = r0 + j * 32;
            int off = row * 128 + c16;
            int sw  = off ^ ((off >> 3) & 0x70);
            cp16(sbuf + t * 16384 + (uint32_t)sw,
                 base + rowbase + (size_t)row * 2048 + k0b + c16);
        }
    }
    asm volatile("cp.async.commit_group;" ::: "memory");
}

__device__ __forceinline__ void g_compute_stage(
    uint32_t sbuf, int lane, int warpM, int warpN, float acc[2][8][4])
{
    const uint32_t Ah = sbuf, Al = sbuf + 16384;
    const uint32_t Bh = sbuf + 32768, Bl = sbuf + 49152;
    #pragma unroll
    for (int kk = 0; kk < 4; kk++) {
        uint32_t ah[2][4], al[2][4], bh[8][2], bl[8][2];
        #pragma unroll
        for (int mt = 0; mt < 2; mt++) {
            int m  = warpM * 32 + mt * 16 + (lane & 15);
            int kb = (kk * 16 + (lane >> 4) * 8) * 2;
            int off = m * 128 + kb;
            int sw  = off ^ ((off >> 3) & 0x70);
            ldsm4(ah[mt], Ah + sw);
            ldsm4(al[mt], Al + sw);
        }
        #pragma unroll
        for (int nb2 = 0; nb2 < 4; nb2++) {
            int n  = warpN * 64 + nb2 * 16 + (lane >> 4) * 8 + (lane & 7);
            int kb = (kk * 16 + ((lane >> 3) & 1) * 8) * 2;
            int off = n * 128 + kb;
            int sw  = off ^ ((off >> 3) & 0x70);
            uint32_t r[4];
            ldsm4(r, Bh + sw);
            bh[nb2 * 2][0] = r[0]; bh[nb2 * 2][1] = r[1];
            bh[nb2 * 2 + 1][0] = r[2]; bh[nb2 * 2 + 1][1] = r[3];
            ldsm4(r, Bl + sw);
            bl[nb2 * 2][0] = r[0]; bl[nb2 * 2][1] = r[1];
            bl[nb2 * 2 + 1][0] = r[2]; bl[nb2 * 2 + 1][1] = r[3];
        }
        #pragma unroll
        for (int mt = 0; mt < 2; mt++)
            #pragma unroll
            for (int nb = 0; nb < 8; nb++) {
                mma16816(acc[mt][nb], ah[mt], bh[nb]);
                mma16816(acc[mt][nb], ah[mt], bl[nb]);
                mma16816(acc[mt][nb], al[mt], bh[nb]);
            }
    }
}

__global__ void __launch_bounds__(256, 1)
mma_gemm(const __nv_bfloat16* __restrict__ Wh, const __nv_bfloat16* __restrict__ Wl,
         const __nv_bfloat16* __restrict__ Xh, const __nv_bfloat16* __restrict__ Xl,
         const float* __restrict__ bias, float* __restrict__ Y)
{
    extern __shared__ char smem[];
    const uint32_t sb = smem_u32(smem);
    const int tid = threadIdx.x, wid = tid >> 5, lane = tid & 31;
    const int warpM = wid & 3, warpN = wid >> 2;
    const int n0 = blockIdx.x * 128, m0 = blockIdx.y * 128, b = blockIdx.z;
    const size_t wrow0 = (size_t)m0 * 2048;
    const size_t xrow0 = ((size_t)b * LSEQ + n0) * 2048;
    const char* cWh = (const char*)Wh; const char* cWl = (const char*)Wl;
    const char* cXh = (const char*)Xh; const char* cXl = (const char*)Xl;

    float acc[2][8][4];
    #pragma unroll
    for (int mt = 0; mt < 2; mt++)
        #pragma unroll
        for (int nb = 0; nb < 8; nb++)
            #pragma unroll
            for (int j = 0; j < 4; j++) acc[mt][nb][j] = 0.f;

    g_load_stage(sb,            0, tid, cWh, cWl, cXh, cXl, wrow0, xrow0);
    g_load_stage(sb + GSTG,     1, tid, cWh, cWl, cXh, cXl, wrow0, xrow0);
    g_load_stage(sb + 2 * GSTG, 2, tid, cWh, cWl, cXh, cXl, wrow0, xrow0);

    int slot = 0;
    for (int st = 0; st < 16; st++) {
        if (st <= 13)      asm volatile("cp.async.wait_group 2;" ::: "memory");
        else if (st == 14) asm volatile("cp.async.wait_group 1;" ::: "memory");
        else               asm volatile("cp.async.wait_group 0;" ::: "memory");
        __syncthreads();
        g_compute_stage(sb + slot * GSTG, lane, warpM, warpN, acc);
        __syncthreads();
        if (st + 3 < 16)
            g_load_stage(sb + slot * GSTG, st + 3, tid, cWh, cWl, cXh, cXl, wrow0, xrow0);
        slot = (slot == 2) ? 0 : slot + 1;
    }

    const int rq = lane >> 2;
    const int cq = (lane & 3) * 2;
    #pragma unroll
    for (int mt = 0; mt < 2; mt++) {
        const int r0 = m0 + warpM * 32 + mt * 16 + rq;
        const float b0 = bias[r0], b1 = bias[r0 + 8];
        const size_t y0 = ((size_t)b * DM + r0) * LSEQ;
        #pragma unroll
        for (int nb = 0; nb < 8; nb++) {
            const int col = n0 + warpN * 64 + nb * 8 + cq;
            float2 v0, v1;
            v0.x = acc[mt][nb][0] + b0; v0.y = acc[mt][nb][1] + b0;
            v1.x = acc[mt][nb][2] + b1; v1.y = acc[mt][nb][3] + b1;
            *(float2*)&Y[y0 + col] = v0;
            *(float2*)&Y[y0 + 8 * LSEQ + col] = v1;
        }
    }
}

// =============================================================================
// Kernel C: per-channel causal long conv + skip — f32x2 packed over r-pairs
// =============================================================================
__global__ void __launch_bounds__(256)
keyconv_kernel(const float* __restrict__ kk, const float* __restrict__ kker,
               const float* __restrict__ dkey, float* __restrict__ out)
{
    __shared__ float xp[4608];
    __shared__ float ks[2048];
    const int c = blockIdx.x, b = blockIdx.y;
    const int tid = threadIdx.x;
    const size_t rowbase = ((size_t)b * DM + c) * LSEQ;

    for (int i = tid; i < 4608; i += 256) xp[i] = 0.f;
    __syncthreads();
    for (int i = tid; i < 2048; i += 256) {
        ks[i] = kker[(size_t)c * LSEQ + i];
        int p = 2048 + i;
        xp[p + (p >> 3)] = kk[rowbase + i];
    }
    __syncthreads();

    const int wid = tid >> 5, lane = tid & 31;
    const int strip = (wid < 4) ? wid : (11 - wid);
    const int l0 = strip * 256 + lane * 8;
    const int jmaxw = strip * 256 + 255;

    ull acc2[4];
    #pragma unroll
    for (int r2 = 0; r2 < 4; r2++) acc2[r2] = 0ull;

    for (int j0 = 0; j0 <= jmaxw; j0 += 8) {
        ull kr2[8];
        #pragma unroll
        for (int s = 0; s < 8; s++) { float kv = ks[j0 + s]; kr2[s] = pk2(kv, kv); }
        float xv[15];
        #pragma unroll
        for (int t = 0; t < 15; t++) {
            int p = 2048 + l0 - j0 - 7 + t;
            xv[t] = xp[p + (p >> 3)];
        }
        ull xv2[14];
        #pragma unroll
        for (int t = 0; t < 14; t++) xv2[t] = pk2(xv[t], xv[t + 1]);
        #pragma unroll
        for (int r2 = 0; r2 < 4; r2++)
            #pragma unroll
            for (int s = 0; s < 8; s++)
                acc2[r2] = fma2(kr2[s], xv2[2 * r2 - s + 7], acc2[r2]);
    }
    const float dk = dkey[c];
    #pragma unroll
    for (int r2 = 0; r2 < 4; r2++) {
        float a0, a1;
        upk2(acc2[r2], a0, a1);
        int p0 = 2048 + l0 + 2 * r2;
        int p1 = p0 + 1;
        out[rowbase + l0 + 2 * r2]     = a0 + xp[p0 + (p0 >> 3)] * dk;
        out[rowbase + l0 + 2 * r2 + 1] = a1 + xp[p1 + (p1 >> 3)] * dk;
    }
}

// =============================================================================
// Kernel D: kernel-weighted linear attention — f32x2 packed over r-pairs
// =============================================================================
__global__ void __launch_bounds__(256)
attn_kernel(const float* __restrict__ gq, const float* __restrict__ gk,
            const float* __restrict__ gv, const float* __restrict__ kerv,
            const float* __restrict__ Dp, float* __restrict__ gy)
{
    extern __shared__ float sm[];
    float* ks = sm;
    float* vs = sm + 8192;
    float* kp = sm + 16384;
    const int h = blockIdx.x, b = blockIdx.y;
    const int tid = threadIdx.x;
    const size_t base = ((size_t)b * DM + (size_t)h * HD) * LSEQ;

    for (int i = tid; i < 8192; i += 256) { ks[i] = gk[base + i]; vs[i] = gv[base + i]; }
    for (int i = tid; i < 4608; i += 256) kp[i] = 0.f;
    __syncthreads();
    for (int j = tid; j < 2048; j += 256) {
        int p = 2048 + j;
        kp[p + (p >> 3)] = kerv[(size_t)h * LSEQ + j];
    }
    __syncthreads();

    const int wid = tid >> 5, lane = tid & 31;
    const int strip = (wid < 4) ? wid : (11 - wid);
    const int l0 = strip * 256 + lane * 8;
    const int mmax = strip * 256 + 255;

    // packed q pairs: q2[d1][r2] = (q[l0+2r2], q[l0+2r2+1])
    ull q2[4][4];
    #pragma unroll
    for (int d1 = 0; d1 < 4; d1++)
        #pragma unroll
        for (int r2 = 0; r2 < 4; r2++) {
            float2 qq = *(const float2*)&gq[base + (size_t)d1 * LSEQ + l0 + 2 * r2];
            q2[d1][r2] = pk2(qq.x, qq.y);
        }

    ull acc2[4][4];
    #pragma unroll
    for (int d = 0; d < 4; d++)
        #pragma unroll
        for (int r2 = 0; r2 < 4; r2++) acc2[d][r2] = 0ull;

    const int pb = 2048 + l0;

    for (int m = 0; m <= mmax; m++) {
        float k0s = ks[m], k1s = ks[2048 + m], k2s = ks[4096 + m], k3s = ks[6144 + m];
        float v0s = vs[m], v1s = vs[2048 + m], v2s = vs[4096 + m], v3s = vs[6144 + m];
        ull kk0 = pk2(k0s, k0s), kk1 = pk2(k1s, k1s);
        ull kk2 = pk2(k2s, k2s), kk3 = pk2(k3s, k3s);
        ull vv0 = pk2(v0s, v0s), vv1 = pk2(v1s, v1s);
        ull vv2 = pk2(v2s, v2s), vv3 = pk2(v3s, v3s);
        #pragma unroll
        for (int r2 = 0; r2 < 4; r2++) {
            ull s = mul2(q2[0][r2], kk0);
            s = fma2(q2[1][r2], kk1, s);
            s = fma2(q2[2][r2], kk2, s);
            s = fma2(q2[3][r2], kk3, s);
            int p0 = pb + 2 * r2 - m;
            int p1 = p0 + 1;
            ull kerp = pk2(kp[p0 + (p0 >> 3)], kp[p1 + (p1 >> 3)]);
            ull w = mul2(s, kerp);
            acc2[0][r2] = fma2(w, vv0, acc2[0][r2]);
            acc2[1][r2] = fma2(w, vv1, acc2[1][r2]);
            acc2[2][r2] = fma2(w, vv2, acc2[2][r2]);
            acc2[3][r2] = fma2(w, vv3, acc2[3][r2]);
        }
    }

    // unpack accumulators
    float acc[4][8];
    #pragma unroll
    for (int d = 0; d < 4; d++)
        #pragma unroll
        for (int r2 = 0; r2 < 4; r2++)
            upk2(acc2[d][r2], acc[d][2 * r2], acc[d][2 * r2 + 1]);

    // D skip: D[h] * (q_l . k_l) * v[d2,l]
    const float Dh = Dp[h];
    float qreg[4][8];
    #pragma unroll
    for (int d1 = 0; d1 < 4; d1++)
        #pragma unroll
        for (int r2 = 0; r2 < 4; r2++)
            upk2(q2[d1][r2], qreg[d1][2 * r2], qreg[d1][2 * r2 + 1]);
    #pragma unroll
    for (int r = 0; r < 8; r++) {
        int l = l0 + r;
        float s = qreg[0][r] * ks[l] + qreg[1][r] * ks[2048 + l]
                + qreg[2][r] * ks[4096 + l] + qreg[3][r] * ks[6144 + l];
        float w = Dh * s;
        acc[0][r] += w * vs[l];
        acc[1][r] += w * vs[2048 + l];
        acc[2][r] += w * vs[4096 + l];
        acc[3][r] += w * vs[6144 + l];
    }

    #pragma unroll
    for (int d2 = 0; d2 < 4; d2++) {
        size_t orow = ((size_t)b * DM + (size_t)d2 * HH + h) * LSEQ + l0;
        #pragma unroll
        for (int r = 0; r < 8; r++) {
            float x = acc[d2][r];
            gy[orow + r] = 0.5f * x * (1.f + erff(x * 0.70710678118654752f));
        }
    }
}

// =============================================================================
extern "C" void kernel_launch(void* const* d_in, const int* in_sizes, int n_in,
                              void* d_out, int out_size)
{
    const float* u       = (const float*)d_in[0];
    const float* q_w     = (const float*)d_in[1];
    const float* q_b     = (const float*)d_in[2];
    const float* k_w     = (const float*)d_in[3];
    const float* k_b     = (const float*)d_in[4];
    const float* v_w     = (const float*)d_in[5];
    const float* v_b     = (const float*)d_in[6];
    const float* kkey_in = (const float*)d_in[7];
    const float* kv_in   = (const float*)d_in[8];
    const float* D_key   = (const float*)d_in[9];
    const float* Dh      = (const float*)d_in[10];
    const float* pw_w    = (const float*)d_in[11];
    const float* pw_b    = (const float*)d_in[12];
    float* out = (float*)d_out;

    float *kkey, *kvk, *q, *k, *v, *kc, *y;
    __nv_bfloat16 *wh, *wl, *xh, *xl;
    cudaGetSymbolAddress((void**)&kkey, g_kkey);
    cudaGetSymbolAddress((void**)&kvk,  g_kvker);
    cudaGetSymbolAddress((void**)&q,    g_q);
    cudaGetSymbolAddress((void**)&k,    g_k);
    cudaGetSymbolAddress((void**)&v,    g_v);
    cudaGetSymbolAddress((void**)&kc,   g_kc);
    cudaGetSymbolAddress((void**)&y,    g_y);
    cudaGetSymbolAddress((void**)&wh,   g_wh);
    cudaGetSymbolAddress((void**)&wl,   g_wl);
    cudaGetSymbolAddress((void**)&xh,   g_xh);
    cudaGetSymbolAddress((void**)&xl,   g_xl);

    const int ATT_SMEM = (8192 + 8192 + 4608) * (int)sizeof(float);
    cudaFuncSetAttribute(attn_kernel, cudaFuncAttributeMaxDynamicSharedMemorySize, ATT_SMEM);
    cudaFuncSetAttribute(mma_gemm, cudaFuncAttributeMaxDynamicSharedMemorySize, 3 * GSTG);

    // 1. build conv kernels
    build_kernels<<<DM, 256>>>(kkey_in, kkey, DM);
    build_kernels<<<HH, 256>>>(kv_in,   kvk,  HH);

    // 2. split weights to bf16 hi/lo
    const int WN = DM * DM;
    wsplit<<<WN / 256, 256>>>(q_w,  wh + 0 * (size_t)WN, wl + 0 * (size_t)WN, WN);
    wsplit<<<WN / 256, 256>>>(k_w,  wh + 1 * (size_t)WN, wl + 1 * (size_t)WN, WN);
    wsplit<<<WN / 256, 256>>>(v_w,  wh + 2 * (size_t)WN, wl + 2 * (size_t)WN, WN);
    wsplit<<<WN / 256, 256>>>(pw_w, wh + 3 * (size_t)WN, wl + 3 * (size_t)WN, WN);

    // 3. transpose + split u -> (b, l, c) bf16
    trans_split<<<dim3(LSEQ / 32, DM / 32, BB), 256>>>(u, xh, xl);

    // 4. q/k/v projections on tensor cores (mma.sync)
    dim3 gg(LSEQ / 128, DM / 128, BB);
    mma_gemm<<<gg, 256, 3 * GSTG>>>(wh + 0 * (size_t)WN, wl + 0 * (size_t)WN, xh, xl, q_b, q);
    mma_gemm<<<gg, 256, 3 * GSTG>>>(wh + 1 * (size_t)WN, wl + 1 * (size_t)WN, xh, xl, k_b, k);
    mma_gemm<<<gg, 256, 3 * GSTG>>>(wh + 2 * (size_t)WN, wl + 2 * (size_t)WN, xh, xl, v_b, v);

    // 5. key-side causal long conv + skip
    keyconv_kernel<<<dim3(DM, BB), 256>>>(k, kkey, D_key, kc);

    // 6. kernel-weighted linear attention + D skip + gelu
    attn_kernel<<<dim3(HH, BB), 256, ATT_SMEM>>>(q, kc, v, kvk, Dh, y);

    // 7. transpose + split y, pointwise projection -> out
    trans_split<<<dim3(LSEQ / 32, DM / 32, BB), 256>>>(y, xh, xl);
    mma_gemm<<<gg, 256, 3 * GSTG>>>(wh + 3 * (size_t)WN, wl + 3 * (size_t)WN, xh, xl, pw_b, out);
}

// round 6
// speedup vs baseline: 1.8294x; 1.0116x over previous
#include <cuda_runtime.h>
#include <cuda_bf16.h>
#include <stdint.h>
#include <math.h>

// Problem constants
#define DM   1024
#define LSEQ 2048
#define BB   4
#define HH   256   // heads
#define HD   4     // head dim

typedef unsigned long long ull;

// ---------------- scratch (device globals; no allocs allowed) ----------------
__device__ float g_kkey [DM * LSEQ];
__device__ float g_kvker[HH * LSEQ];
__device__ float g_q [BB * DM * LSEQ];
__device__ float g_k [BB * DM * LSEQ];
__device__ float g_v [BB * DM * LSEQ];
__device__ float g_kc[BB * DM * LSEQ];
__device__ float g_y [BB * DM * LSEQ];
__device__ float g_bias[3 * DM];                // packed q/k/v bias
// bf16 split operands for tensor-core GEMMs
__device__ __nv_bfloat16 g_wh[4][DM * DM];      // q,k,v,pw weight hi (contiguous!)
__device__ __nv_bfloat16 g_wl[4][DM * DM];
__device__ __nv_bfloat16 g_xh[BB * LSEQ * DM];
__device__ __nv_bfloat16 g_xl[BB * LSEQ * DM];

// ======================= helpers (baseline ISA only) =========================
__device__ __forceinline__ uint32_t smem_u32(const void* p) {
    uint32_t a;
    asm("{ .reg .u64 t; cvta.to.shared.u64 t, %1; cvt.u32.u64 %0, t; }" : "=r"(a) : "l"(p));
    return a;
}
__device__ __forceinline__ void cp16(uint32_t dst, const void* src) {
    asm volatile("cp.async.cg.shared.global [%0], [%1], 16;" :: "r"(dst), "l"(src));
}
__device__ __forceinline__ void ldsm4(uint32_t* r, uint32_t addr) {
    asm volatile("ldmatrix.sync.aligned.m8n8.x4.shared.b16 {%0,%1,%2,%3}, [%4];"
        : "=r"(r[0]), "=r"(r[1]), "=r"(r[2]), "=r"(r[3]) : "r"(addr));
}
__device__ __forceinline__ void mma16816(float* d, const uint32_t* a, const uint32_t* b) {
    asm volatile("mma.sync.aligned.m16n8k16.row.col.f32.bf16.bf16.f32 "
        "{%0,%1,%2,%3}, {%4,%5,%6,%7}, {%8,%9}, {%0,%1,%2,%3};"
        : "+f"(d[0]), "+f"(d[1]), "+f"(d[2]), "+f"(d[3])
        : "r"(a[0]), "r"(a[1]), "r"(a[2]), "r"(a[3]), "r"(b[0]), "r"(b[1]));
}
// ---------------- packed fp32x2 (Blackwell) ----------------
__device__ __forceinline__ ull pk2(float a, float b) {
    ull d; asm("mov.b64 %0, {%1, %2};" : "=l"(d) : "f"(a), "f"(b)); return d;
}
__device__ __forceinline__ ull mul2(ull a, ull b) {
    ull d; asm("mul.rn.f32x2 %0, %1, %2;" : "=l"(d) : "l"(a), "l"(b)); return d;
}
__device__ __forceinline__ ull fma2(ull a, ull b, ull c) {
    ull d; asm("fma.rn.f32x2 %0, %1, %2, %3;" : "=l"(d) : "l"(a), "l"(b), "l"(c)); return d;
}
__device__ __forceinline__ void upk2(ull v, float& a, float& b) {
    asm("mov.b64 {%0, %1}, %2;" : "=f"(a), "=f"(b) : "l"(v));
}

// =============================================================================
// Kernel A: build multi-scale interpolated kernels — single launch (1280 rows)
// =============================================================================
__global__ void build_kernels(const float* __restrict__ src_key,
                              const float* __restrict__ src_val,
                              float* __restrict__ dst_key,
                              float* __restrict__ dst_val)
{
    const int cc  = blockIdx.x;
    const int c   = (cc < DM) ? cc : cc - DM;
    const int nch = (cc < DM) ? DM : HH;
    const float* src = (cc < DM) ? src_key : src_val;
    float* dst       = (cc < DM) ? dst_key : dst_val;
    const int tid = threadIdx.x;
    float vals[8];
    float ss = 0.f;
    #pragma unroll
    for (int r = 0; r < 8; r++) {
        int j = tid * 8 + r;
        int i, start;
        if      (j <   64) { i = 0; start = 0;    }
        else if (j <  128) { i = 1; start = 64;   }
        else if (j <  256) { i = 2; start = 128;  }
        else if (j <  512) { i = 3; start = 256;  }
        else if (j < 1024) { i = 4; start = 512;  }
        else               { i = 5; start = 1024; }
        int   s    = (i <= 1) ? 1 : (1 << (i - 1));
        float mult = (float)(1 << (5 - i));
        int   jj   = j - start;
        float pos  = ((float)jj + 0.5f) / (float)s - 0.5f;
        pos = fminf(fmaxf(pos, 0.f), 63.f);
        int   lo = (int)floorf(pos);
        int   hi = min(lo + 1, 63);
        float w  = pos - (float)lo;
        const float* row = src + ((size_t)i * nch + c) * 64;
        float v = (row[lo] * (1.f - w) + row[hi] * w) * mult;
        vals[r] = v;
        ss += v * v;
    }
    __shared__ float red[256];
    red[tid] = ss;
    __syncthreads();
    for (int off = 128; off > 0; off >>= 1) {
        if (tid < off) red[tid] += red[tid + off];
        __syncthreads();
    }
    float inv = 1.f / sqrtf(red[0]);
    #pragma unroll
    for (int r = 0; r < 8; r++)
        dst[(size_t)c * LSEQ + tid * 8 + r] = vals[r] * inv;
}

// =============================================================================
// bf16 hi/lo split of all 4 weight matrices, one launch. grid (4096, 4)
// =============================================================================
__global__ void wsplit4(const float* __restrict__ w0, const float* __restrict__ w1,
                        const float* __restrict__ w2, const float* __restrict__ w3,
                        __nv_bfloat16* __restrict__ h, __nv_bfloat16* __restrict__ l)
{
    const int m = blockIdx.y;
    const float* w = (m == 0) ? w0 : (m == 1) ? w1 : (m == 2) ? w2 : w3;
    int i = blockIdx.x * 256 + threadIdx.x;
    size_t o = (size_t)m * (DM * DM) + i;
    float x = w[i];
    __nv_bfloat16 hh = __float2bfloat16(x);
    h[o] = hh;
    l[o] = __float2bfloat16(x - __bfloat162float(hh));
}

__global__ void pack_bias(const float* __restrict__ qb, const float* __restrict__ kb,
                          const float* __restrict__ vb, float* __restrict__ dst)
{
    int i = blockIdx.x * 256 + threadIdx.x;   // 3072
    dst[i] = (i < DM) ? qb[i] : (i < 2 * DM) ? kb[i - DM] : vb[i - 2 * DM];
}

// =============================================================================
// transpose (b, C, L) fp32 -> (b, L, C) bf16 hi/lo
// =============================================================================
__global__ void __launch_bounds__(256)
trans_split(const float* __restrict__ in, __nv_bfloat16* __restrict__ oh,
            __nv_bfloat16* __restrict__ ol)
{
    __shared__ float t[32][33];
    const int tx = threadIdx.x & 31, ty = threadIdx.x >> 5;
    const int l0 = blockIdx.x * 32, c0 = blockIdx.y * 32, b = blockIdx.z;
    #pragma unroll
    for (int i = 0; i < 4; i++) {
        int c = c0 + ty + i * 8;
        t[ty + i * 8][tx] = in[((size_t)b * DM + c) * LSEQ + l0 + tx];
    }
    __syncthreads();
    #pragma unroll
    for (int i = 0; i < 4; i++) {
        int l = l0 + ty + i * 8;
        float x = t[tx][ty + i * 8];
        __nv_bfloat16 h = __float2bfloat16(x);
        __nv_bfloat16 lo = __float2bfloat16(x - __bfloat162float(h));
        size_t o = ((size_t)b * LSEQ + l) * DM + c0 + tx;
        oh[o] = h; ol[o] = lo;
    }
}

// =============================================================================
// mma.sync bf16 split GEMM, stacked-M variant. W rows are stacked (up to 3072);
// output pointer selected per 1024-row group. 3-stage cp.async, 192KB smem.
// =============================================================================
#define GSTG 65536

__device__ __forceinline__ void g_load_stage(
    uint32_t sbuf, int stage, int tid,
    const char* Wh, const char* Wl, const char* Xh, const char* Xl,
    size_t wrow0, size_t xrow0)
{
    const int k0b = stage * 128;
    const int c16 = (tid & 7) * 16;
    const int r0  = tid >> 3;
    #pragma unroll
    for (int t = 0; t < 4; t++) {
        const char* base = (t == 0) ? Wh : (t == 1) ? Wl : (t == 2) ? Xh : Xl;
        const size_t rowbase = (t < 2) ? wrow0 : xrow0;
        #pragma unroll
        for (int j = 0; j < 4; j++) {
            int row = r0 + j * 32;
            int off = row * 128 + c16;
            int sw  = off ^ ((off >> 3) & 0x70);
            cp16(sbuf + t * 16384 + (uint32_t)sw,
                 base + rowbase + (size_t)row * 2048 + k0b + c16);
        }
    }
    asm volatile("cp.async.commit_group;" ::: "memory");
}

__device__ __forceinline__ void g_compute_stage(
    uint32_t sbuf, int lane, int warpM, int warpN, float acc[2][8][4])
{
    const uint32_t Ah = sbuf, Al = sbuf + 16384;
    const uint32_t Bh = sbuf + 32768, Bl = sbuf + 49152;
    #pragma unroll
    for (int kk = 0; kk < 4; kk++) {
        uint32_t ah[2][4], al[2][4], bh[8][2], bl[8][2];
        #pragma unroll
        for (int mt = 0; mt < 2; mt++) {
            int m  = warpM * 32 + mt * 16 + (lane & 15);
            int kb = (kk * 16 + (lane >> 4) * 8) * 2;
            int off = m * 128 + kb;
            int sw  = off ^ ((off >> 3) & 0x70);
            ldsm4(ah[mt], Ah + sw);
            ldsm4(al[mt], Al + sw);
        }
        #pragma unroll
        for (int nb2 = 0; nb2 < 4; nb2++) {
            int n  = warpN * 64 + nb2 * 16 + (lane >> 4) * 8 + (lane & 7);
            int kb = (kk * 16 + ((lane >> 3) & 1) * 8) * 2;
            int off = n * 128 + kb;
            int sw  = off ^ ((off >> 3) & 0x70);
            uint32_t r[4];
            ldsm4(r, Bh + sw);
            bh[nb2 * 2][0] = r[0]; bh[nb2 * 2][1] = r[1];
            bh[nb2 * 2 + 1][0] = r[2]; bh[nb2 * 2 + 1][1] = r[3];
            ldsm4(r, Bl + sw);
            bl[nb2 * 2][0] = r[0]; bl[nb2 * 2][1] = r[1];
            bl[nb2 * 2 + 1][0] = r[2]; bl[nb2 * 2 + 1][1] = r[3];
        }
        #pragma unroll
        for (int mt = 0; mt < 2; mt++)
            #pragma unroll
            for (int nb = 0; nb < 8; nb++) {
                mma16816(acc[mt][nb], ah[mt], bh[nb]);
                mma16816(acc[mt][nb], ah[mt], bl[nb]);
                mma16816(acc[mt][nb], al[mt], bh[nb]);
            }
    }
}

__global__ void __launch_bounds__(256, 1)
mma_gemm(const __nv_bfloat16* __restrict__ Wh, const __nv_bfloat16* __restrict__ Wl,
         const __nv_bfloat16* __restrict__ Xh, const __nv_bfloat16* __restrict__ Xl,
         const float* __restrict__ bias,
         float* __restrict__ Y0, float* __restrict__ Y1, float* __restrict__ Y2)
{
    extern __shared__ char smem[];
    const uint32_t sb = smem_u32(smem);
    const int tid = threadIdx.x, wid = tid >> 5, lane = tid & 31;
    const int warpM = wid & 3, warpN = wid >> 2;
    const int n0 = blockIdx.x * 128, m0 = blockIdx.y * 128, b = blockIdx.z;
    const size_t wrow0 = (size_t)m0 * 2048;          // bytes into stacked W
    const size_t xrow0 = ((size_t)b * LSEQ + n0) * 2048;
    const char* cWh = (const char*)Wh; const char* cWl = (const char*)Wl;
    const char* cXh = (const char*)Xh; const char* cXl = (const char*)Xl;

    float acc[2][8][4];
    #pragma unroll
    for (int mt = 0; mt < 2; mt++)
        #pragma unroll
        for (int nb = 0; nb < 8; nb++)
            #pragma unroll
            for (int j = 0; j < 4; j++) acc[mt][nb][j] = 0.f;

    g_load_stage(sb,            0, tid, cWh, cWl, cXh, cXl, wrow0, xrow0);
    g_load_stage(sb + GSTG,     1, tid, cWh, cWl, cXh, cXl, wrow0, xrow0);
    g_load_stage(sb + 2 * GSTG, 2, tid, cWh, cWl, cXh, cXl, wrow0, xrow0);

    int slot = 0;
    for (int st = 0; st < 16; st++) {
        if (st <= 13)      asm volatile("cp.async.wait_group 2;" ::: "memory");
        else if (st == 14) asm volatile("cp.async.wait_group 1;" ::: "memory");
        else               asm volatile("cp.async.wait_group 0;" ::: "memory");
        __syncthreads();
        g_compute_stage(sb + slot * GSTG, lane, warpM, warpN, acc);
        __syncthreads();
        if (st + 3 < 16)
            g_load_stage(sb + slot * GSTG, st + 3, tid, cWh, cWl, cXh, cXl, wrow0, xrow0);
        slot = (slot == 2) ? 0 : slot + 1;
    }

    // whole CTA belongs to one 1024-row group
    const int mat = m0 >> 10;
    float* Y = (mat == 0) ? Y0 : (mat == 1) ? Y1 : Y2;
    const int rq = lane >> 2;
    const int cq = (lane & 3) * 2;
    #pragma unroll
    for (int mt = 0; mt < 2; mt++) {
        const int rs = m0 + warpM * 32 + mt * 16 + rq;       // stacked row
        const int row = rs & 1023;
        const float b0 = bias[rs], b1 = bias[rs + 8];
        const size_t y0 = ((size_t)b * DM + row) * LSEQ;
        #pragma unroll
        for (int nb = 0; nb < 8; nb++) {
            const int col = n0 + warpN * 64 + nb * 8 + cq;
            float2 v0, v1;
            v0.x = acc[mt][nb][0] + b0; v0.y = acc[mt][nb][1] + b0;
            v1.x = acc[mt][nb][2] + b1; v1.y = acc[mt][nb][3] + b1;
            *(float2*)&Y[y0 + col] = v0;
            *(float2*)&Y[y0 + 8 * LSEQ + col] = v1;
        }
    }
}

// =============================================================================
// Kernel C: per-channel causal long conv + skip.  f32x2, 16 l per thread,
// 2 channels per block (8 warps: 4 strips x 2 channels, SMSP-balanced).
// padding p + (p>>4): lane stride 16 -> 17 (gcd(17,32)=1, conflict-free).
// dynamic smem: xp[2][4608] + ks[2][2048] = 53248 B
// =============================================================================
__global__ void __launch_bounds__(256)
keyconv_kernel(const float* __restrict__ kk, const float* __restrict__ kker,
               const float* __restrict__ dkey, float* __restrict__ out)
{
    extern __shared__ float dsm[];
    float* xp0 = dsm;               // 4608
    float* xp1 = dsm + 4608;        // 4608
    float* ks0 = dsm + 9216;        // 2048
    float* ks1 = dsm + 11264;       // 2048
    const int c0 = blockIdx.x * 2, b = blockIdx.y;
    const int tid = threadIdx.x;
    const size_t rb0 = ((size_t)b * DM + c0) * LSEQ;
    const size_t rb1 = rb0 + LSEQ;

    for (int i = tid; i < 4608; i += 256) { xp0[i] = 0.f; xp1[i] = 0.f; }
    __syncthreads();
    for (int i = tid; i < 2048; i += 256) {
        ks0[i] = kker[(size_t)c0 * LSEQ + i];
        ks1[i] = kker[(size_t)(c0 + 1) * LSEQ + i];
        int p = 2048 + i;
        int a = p + (p >> 4);
        xp0[a] = kk[rb0 + i];
        xp1[a] = kk[rb1 + i];
    }
    __syncthreads();

    const int wid = tid >> 5, lane = tid & 31;
    const int ch = (wid < 4) ? 0 : 1;
    const int strip = (wid < 4) ? wid : (7 - wid);   // FIXED: 3,2,1,0 for wid=4..7
    float* X = ch ? xp1 : xp0;
    float* K = ch ? ks1 : ks0;
    const int c = c0 + ch;
    const size_t rowbase = ch ? rb1 : rb0;
    const int l0 = strip * 512 + lane * 16;
    const int jmax = strip * 512 + 511;

    ull acc2[8];
    #pragma unroll
    for (int r2 = 0; r2 < 8; r2++) acc2[r2] = 0ull;

    for (int j0 = 0; j0 <= jmax; j0 += 8) {
        ull kr2[8];
        #pragma unroll
        for (int s = 0; s < 8; s++) { float kv = K[j0 + s]; kr2[s] = pk2(kv, kv); }
        float xv[23];
        #pragma unroll
        for (int t = 0; t < 23; t++) {
            int p = 2048 + l0 - j0 - 7 + t;
            xv[t] = X[p + (p >> 4)];
        }
        ull xv2[22];
        #pragma unroll
        for (int t = 0; t < 22; t++) xv2[t] = pk2(xv[t], xv[t + 1]);
        #pragma unroll
        for (int r2 = 0; r2 < 8; r2++)
            #pragma unroll
            for (int s = 0; s < 8; s++)
                acc2[r2] = fma2(kr2[s], xv2[2 * r2 - s + 7], acc2[r2]);
    }
    const float dk = dkey[c];
    #pragma unroll
    for (int r2 = 0; r2 < 8; r2++) {
        float a0, a1;
        upk2(acc2[r2], a0, a1);
        int p0 = 2048 + l0 + 2 * r2;
        int p1 = p0 + 1;
        out[rowbase + l0 + 2 * r2]     = a0 + X[p0 + (p0 >> 4)] * dk;
        out[rowbase + l0 + 2 * r2 + 1] = a1 + X[p1 + (p1 >> 4)] * dk;
    }
}

// =============================================================================
// Kernel D: kernel-weighted linear attention — f32x2 (unchanged from R4)
// =============================================================================
__global__ void __launch_bounds__(256)
attn_kernel(const float* __restrict__ gq, const float* __restrict__ gk,
            const float* __restrict__ gv, const float* __restrict__ kerv,
            const float* __restrict__ Dp, float* __restrict__ gy)
{
    extern __shared__ float sm[];
    float* ks = sm;
    float* vs = sm + 8192;
    float* kp = sm + 16384;
    const int h = blockIdx.x, b = blockIdx.y;
    const int tid = threadIdx.x;
    const size_t base = ((size_t)b * DM + (size_t)h * HD) * LSEQ;

    for (int i = tid; i < 8192; i += 256) { ks[i] = gk[base + i]; vs[i] = gv[base + i]; }
    for (int i = tid; i < 4608; i += 256) kp[i] = 0.f;
    __syncthreads();
    for (int j = tid; j < 2048; j += 256) {
        int p = 2048 + j;
        kp[p + (p >> 3)] = kerv[(size_t)h * LSEQ + j];
    }
    __syncthreads();

    const int wid = tid >> 5, lane = tid & 31;
    const int strip = (wid < 4) ? wid : (11 - wid);
    const int l0 = strip * 256 + lane * 8;
    const int mmax = strip * 256 + 255;

    ull q2[4][4];
    #pragma unroll
    for (int d1 = 0; d1 < 4; d1++)
        #pragma unroll
        for (int r2 = 0; r2 < 4; r2++) {
            float2 qq = *(const float2*)&gq[base + (size_t)d1 * LSEQ + l0 + 2 * r2];
            q2[d1][r2] = pk2(qq.x, qq.y);
        }

    ull acc2[4][4];
    #pragma unroll
    for (int d = 0; d < 4; d++)
        #pragma unroll
        for (int r2 = 0; r2 < 4; r2++) acc2[d][r2] = 0ull;

    const int pb = 2048 + l0;

    for (int m = 0; m <= mmax; m++) {
        float k0s = ks[m], k1s = ks[2048 + m], k2s = ks[4096 + m], k3s = ks[6144 + m];
        float v0s = vs[m], v1s = vs[2048 + m], v2s = vs[4096 + m], v3s = vs[6144 + m];
        ull kk0 = pk2(k0s, k0s), kk1 = pk2(k1s, k1s);
        ull kk2 = pk2(k2s, k2s), kk3 = pk2(k3s, k3s);
        ull vv0 = pk2(v0s, v0s), vv1 = pk2(v1s, v1s);
        ull vv2 = pk2(v2s, v2s), vv3 = pk2(v3s, v3s);
        #pragma unroll
        for (int r2 = 0; r2 < 4; r2++) {
            ull s = mul2(q2[0][r2], kk0);
            s = fma2(q2[1][r2], kk1, s);
            s = fma2(q2[2][r2], kk2, s);
            s = fma2(q2[3][r2], kk3, s);
            int p0 = pb + 2 * r2 - m;
            int p1 = p0 + 1;
            ull kerp = pk2(kp[p0 + (p0 >> 3)], kp[p1 + (p1 >> 3)]);
            ull w = mul2(s, kerp);
            acc2[0][r2] = fma2(w, vv0, acc2[0][r2]);
            acc2[1][r2] = fma2(w, vv1, acc2[1][r2]);
            acc2[2][r2] = fma2(w, vv2, acc2[2][r2]);
            acc2[3][r2] = fma2(w, vv3, acc2[3][r2]);
        }
    }

    float acc[4][8];
    #pragma unroll
    for (int d = 0; d < 4; d++)
        #pragma unroll
        for (int r2 = 0; r2 < 4; r2++)
            upk2(acc2[d][r2], acc[d][2 * r2], acc[d][2 * r2 + 1]);

    const float Dh = Dp[h];
    float qreg[4][8];
    #pragma unroll
    for (int d1 = 0; d1 < 4; d1++)
        #pragma unroll
        for (int r2 = 0; r2 < 4; r2++)
            upk2(q2[d1][r2], qreg[d1][2 * r2], qreg[d1][2 * r2 + 1]);
    #pragma unroll
    for (int r = 0; r < 8; r++) {
        int l = l0 + r;
        float s = qreg[0][r] * ks[l] + qreg[1][r] * ks[2048 + l]
                + qreg[2][r] * ks[4096 + l] + qreg[3][r] * ks[6144 + l];
        float w = Dh * s;
        acc[0][r] += w * vs[l];
        acc[1][r] += w * vs[2048 + l];
        acc[2][r] += w * vs[4096 + l];
        acc[3][r] += w * vs[6144 + l];
    }

    #pragma unroll
    for (int d2 = 0; d2 < 4; d2++) {
        size_t orow = ((size_t)b * DM + (size_t)d2 * HH + h) * LSEQ + l0;
        #pragma unroll
        for (int r = 0; r < 8; r++) {
            float x = acc[d2][r];
            gy[orow + r] = 0.5f * x * (1.f + erff(x * 0.70710678118654752f));
        }
    }
}

// =============================================================================
extern "C" void kernel_launch(void* const* d_in, const int* in_sizes, int n_in,
                              void* d_out, int out_size)
{
    const float* u       = (const float*)d_in[0];
    const float* q_w     = (const float*)d_in[1];
    const float* q_b     = (const float*)d_in[2];
    const float* k_w     = (const float*)d_in[3];
    const float* k_b     = (const float*)d_in[4];
    const float* v_w     = (const float*)d_in[5];
    const float* v_b     = (const float*)d_in[6];
    const float* kkey_in = (const float*)d_in[7];
    const float* kv_in   = (const float*)d_in[8];
    const float* D_key   = (const float*)d_in[9];
    const float* Dh      = (const float*)d_in[10];
    const float* pw_w    = (const float*)d_in[11];
    const float* pw_b    = (const float*)d_in[12];
    float* out = (float*)d_out;

    float *kkey, *kvk, *q, *k, *v, *kc, *y, *bias;
    __nv_bfloat16 *wh, *wl, *xh, *xl;
    cudaGetSymbolAddress((void**)&kkey, g_kkey);
    cudaGetSymbolAddress((void**)&kvk,  g_kvker);
    cudaGetSymbolAddress((void**)&q,    g_q);
    cudaGetSymbolAddress((void**)&k,    g_k);
    cudaGetSymbolAddress((void**)&v,    g_v);
    cudaGetSymbolAddress((void**)&kc,   g_kc);
    cudaGetSymbolAddress((void**)&y,    g_y);
    cudaGetSymbolAddress((void**)&bias, g_bias);
    cudaGetSymbolAddress((void**)&wh,   g_wh);
    cudaGetSymbolAddress((void**)&wl,   g_wl);
    cudaGetSymbolAddress((void**)&xh,   g_xh);
    cudaGetSymbolAddress((void**)&xl,   g_xl);

    const int ATT_SMEM = (8192 + 8192 + 4608) * (int)sizeof(float);   // 83968
    const int KC_SMEM  = (2 * 4608 + 2 * 2048) * (int)sizeof(float);  // 53248
    cudaFuncSetAttribute(attn_kernel, cudaFuncAttributeMaxDynamicSharedMemorySize, ATT_SMEM);
    cudaFuncSetAttribute(keyconv_kernel, cudaFuncAttributeMaxDynamicSharedMemorySize, KC_SMEM);
    cudaFuncSetAttribute(mma_gemm, cudaFuncAttributeMaxDynamicSharedMemorySize, 3 * GSTG);

    // 1. build conv kernels (merged launch)
    build_kernels<<<DM + HH, 256>>>(kkey_in, kv_in, kkey, kvk);

    // 2. split weights to bf16 hi/lo (merged) + pack qkv biases
    wsplit4<<<dim3(DM * DM / 256, 4), 256>>>(q_w, k_w, v_w, pw_w, wh, wl);
    pack_bias<<<3 * DM / 256, 256>>>(q_b, k_b, v_b, bias);

    // 3. transpose + split u -> (b, l, c) bf16
    trans_split<<<dim3(LSEQ / 32, DM / 32, BB), 256>>>(u, xh, xl);

    // 4. merged q/k/v projection (stacked M = 3072)
    mma_gemm<<<dim3(LSEQ / 128, 3 * DM / 128, BB), 256, 3 * GSTG>>>(
        wh, wl, xh, xl, bias, q, k, v);

    // 5. key-side causal long conv + skip
    keyconv_kernel<<<dim3(DM / 2, BB), 256, KC_SMEM>>>(k, kkey, D_key, kc);

    // 6. kernel-weighted linear attention + D skip + gelu
    attn_kernel<<<dim3(HH, BB), 256, ATT_SMEM>>>(q, kc, v, kvk, Dh, y);

    // 7. transpose + split y, pointwise projection -> out
    trans_split<<<dim3(LSEQ / 32, DM / 32, BB), 256>>>(y, xh, xl);
    mma_gemm<<<dim3(LSEQ / 128, DM / 128, BB), 256, 3 * GSTG>>>(
        wh + 3 * (size_t)(DM * DM), wl + 3 * (size_t)(DM * DM), xh, xl, pw_b, out, out, out);
}

// round 7
// speedup vs baseline: 1.8624x; 1.0181x over previous
#include <cuda_runtime.h>
#include <cuda_bf16.h>
#include <stdint.h>
#include <math.h>

// Problem constants
#define DM   1024
#define LSEQ 2048
#define BB   4
#define HH   256   // heads
#define HD   4     // head dim

typedef unsigned long long ull;

// ---------------- scratch (device globals; no allocs allowed) ----------------
__device__ float g_kkey [DM * LSEQ];
__device__ float g_kvker[HH * LSEQ];
__device__ float g_q [BB * DM * LSEQ];
__device__ float g_k [BB * DM * LSEQ];
__device__ float g_v [BB * DM * LSEQ];
__device__ float g_kc[BB * DM * LSEQ];
__device__ float g_y [BB * DM * LSEQ];
__device__ float g_bias[3 * DM];                // packed q/k/v bias
// bf16 split operands for tensor-core GEMMs
__device__ __nv_bfloat16 g_wh[4][DM * DM];      // q,k,v,pw weight hi (contiguous!)
__device__ __nv_bfloat16 g_wl[4][DM * DM];
__device__ __nv_bfloat16 g_xh[BB * LSEQ * DM];
__device__ __nv_bfloat16 g_xl[BB * LSEQ * DM];

// ======================= helpers (baseline ISA only) =========================
__device__ __forceinline__ uint32_t smem_u32(const void* p) {
    uint32_t a;
    asm("{ .reg .u64 t; cvta.to.shared.u64 t, %1; cvt.u32.u64 %0, t; }" : "=r"(a) : "l"(p));
    return a;
}
__device__ __forceinline__ void cp16(uint32_t dst, const void* src) {
    asm volatile("cp.async.cg.shared.global [%0], [%1], 16;" :: "r"(dst), "l"(src));
}
__device__ __forceinline__ void ldsm4(uint32_t* r, uint32_t addr) {
    asm volatile("ldmatrix.sync.aligned.m8n8.x4.shared.b16 {%0,%1,%2,%3}, [%4];"
        : "=r"(r[0]), "=r"(r[1]), "=r"(r[2]), "=r"(r[3]) : "r"(addr));
}
__device__ __forceinline__ void mma16816(float* d, const uint32_t* a, const uint32_t* b) {
    asm volatile("mma.sync.aligned.m16n8k16.row.col.f32.bf16.bf16.f32 "
        "{%0,%1,%2,%3}, {%4,%5,%6,%7}, {%8,%9}, {%0,%1,%2,%3};"
        : "+f"(d[0]), "+f"(d[1]), "+f"(d[2]), "+f"(d[3])
        : "r"(a[0]), "r"(a[1]), "r"(a[2]), "r"(a[3]), "r"(b[0]), "r"(b[1]));
}
// ---------------- packed fp32x2 (Blackwell) ----------------
__device__ __forceinline__ ull pk2(float a, float b) {
    ull d; asm("mov.b64 %0, {%1, %2};" : "=l"(d) : "f"(a), "f"(b)); return d;
}
__device__ __forceinline__ ull mul2(ull a, ull b) {
    ull d; asm("mul.rn.f32x2 %0, %1, %2;" : "=l"(d) : "l"(a), "l"(b)); return d;
}
__device__ __forceinline__ ull fma2(ull a, ull b, ull c) {
    ull d; asm("fma.rn.f32x2 %0, %1, %2, %3;" : "=l"(d) : "l"(a), "l"(b), "l"(c)); return d;
}
__device__ __forceinline__ void upk2(ull v, float& a, float& b) {
    asm("mov.b64 {%0, %1}, %2;" : "=f"(a), "=f"(b) : "l"(v));
}

// =============================================================================
// Kernel A: build multi-scale interpolated kernels — single launch (1280 rows)
// =============================================================================
__global__ void build_kernels(const float* __restrict__ src_key,
                              const float* __restrict__ src_val,
                              float* __restrict__ dst_key,
                              float* __restrict__ dst_val)
{
    const int cc  = blockIdx.x;
    const int c   = (cc < DM) ? cc : cc - DM;
    const int nch = (cc < DM) ? DM : HH;
    const float* src = (cc < DM) ? src_key : src_val;
    float* dst       = (cc < DM) ? dst_key : dst_val;
    const int tid = threadIdx.x;
    float vals[8];
    float ss = 0.f;
    #pragma unroll
    for (int r = 0; r < 8; r++) {
        int j = tid * 8 + r;
        int i, start;
        if      (j <   64) { i = 0; start = 0;    }
        else if (j <  128) { i = 1; start = 64;   }
        else if (j <  256) { i = 2; start = 128;  }
        else if (j <  512) { i = 3; start = 256;  }
        else if (j < 1024) { i = 4; start = 512;  }
        else               { i = 5; start = 1024; }
        int   s    = (i <= 1) ? 1 : (1 << (i - 1));
        float mult = (float)(1 << (5 - i));
        int   jj   = j - start;
        float pos  = ((float)jj + 0.5f) / (float)s - 0.5f;
        pos = fminf(fmaxf(pos, 0.f), 63.f);
        int   lo = (int)floorf(pos);
        int   hi = min(lo + 1, 63);
        float w  = pos - (float)lo;
        const float* row = src + ((size_t)i * nch + c) * 64;
        float v = (row[lo] * (1.f - w) + row[hi] * w) * mult;
        vals[r] = v;
        ss += v * v;
    }
    __shared__ float red[256];
    red[tid] = ss;
    __syncthreads();
    for (int off = 128; off > 0; off >>= 1) {
        if (tid < off) red[tid] += red[tid + off];
        __syncthreads();
    }
    float inv = 1.f / sqrtf(red[0]);
    #pragma unroll
    for (int r = 0; r < 8; r++)
        dst[(size_t)c * LSEQ + tid * 8 + r] = vals[r] * inv;
}

// =============================================================================
// bf16 hi/lo split of all 4 weight matrices, one launch. grid (4096, 4)
// =============================================================================
__global__ void wsplit4(const float* __restrict__ w0, const float* __restrict__ w1,
                        const float* __restrict__ w2, const float* __restrict__ w3,
                        __nv_bfloat16* __restrict__ h, __nv_bfloat16* __restrict__ l)
{
    const int m = blockIdx.y;
    const float* w = (m == 0) ? w0 : (m == 1) ? w1 : (m == 2) ? w2 : w3;
    int i = blockIdx.x * 256 + threadIdx.x;
    size_t o = (size_t)m * (DM * DM) + i;
    float x = w[i];
    __nv_bfloat16 hh = __float2bfloat16(x);
    h[o] = hh;
    l[o] = __float2bfloat16(x - __bfloat162float(hh));
}

__global__ void pack_bias(const float* __restrict__ qb, const float* __restrict__ kb,
                          const float* __restrict__ vb, float* __restrict__ dst)
{
    int i = blockIdx.x * 256 + threadIdx.x;   // 3072
    dst[i] = (i < DM) ? qb[i] : (i < 2 * DM) ? kb[i - DM] : vb[i - 2 * DM];
}

// =============================================================================
// transpose (b, C, L) fp32 -> (b, L, C) bf16 hi/lo
// =============================================================================
__global__ void __launch_bounds__(256)
trans_split(const float* __restrict__ in, __nv_bfloat16* __restrict__ oh,
            __nv_bfloat16* __restrict__ ol)
{
    __shared__ float t[32][33];
    const int tx = threadIdx.x & 31, ty = threadIdx.x >> 5;
    const int l0 = blockIdx.x * 32, c0 = blockIdx.y * 32, b = blockIdx.z;
    #pragma unroll
    for (int i = 0; i < 4; i++) {
        int c = c0 + ty + i * 8;
        t[ty + i * 8][tx] = in[((size_t)b * DM + c) * LSEQ + l0 + tx];
    }
    __syncthreads();
    #pragma unroll
    for (int i = 0; i < 4; i++) {
        int l = l0 + ty + i * 8;
        float x = t[tx][ty + i * 8];
        __nv_bfloat16 h = __float2bfloat16(x);
        __nv_bfloat16 lo = __float2bfloat16(x - __bfloat162float(h));
        size_t o = ((size_t)b * LSEQ + l) * DM + c0 + tx;
        oh[o] = h; ol[o] = lo;
    }
}

// =============================================================================
// mma.sync bf16 split GEMM, stacked-M variant (unchanged from R6)
// =============================================================================
#define GSTG 65536

__device__ __forceinline__ void g_load_stage(
    uint32_t sbuf, int stage, int tid,
    const char* Wh, const char* Wl, const char* Xh, const char* Xl,
    size_t wrow0, size_t xrow0)
{
    const int k0b = stage * 128;
    const int c16 = (tid & 7) * 16;
    const int r0  = tid >> 3;
    #pragma unroll
    for (int t = 0; t < 4; t++) {
        const char* base = (t == 0) ? Wh : (t == 1) ? Wl : (t == 2) ? Xh : Xl;
        const size_t rowbase = (t < 2) ? wrow0 : xrow0;
        #pragma unroll
        for (int j = 0; j < 4; j++) {
            int row = r0 + j * 32;
            int off = row * 128 + c16;
            int sw  = off ^ ((off >> 3) & 0x70);
            cp16(sbuf + t * 16384 + (uint32_t)sw,
                 base + rowbase + (size_t)row * 2048 + k0b + c16);
        }
    }
    asm volatile("cp.async.commit_group;" ::: "memory");
}

__device__ __forceinline__ void g_compute_stage(
    uint32_t sbuf, int lane, int warpM, int warpN, float acc[2][8][4])
{
    const uint32_t Ah = sbuf, Al = sbuf + 16384;
    const uint32_t Bh = sbuf + 32768, Bl = sbuf + 49152;
    #pragma unroll
    for (int kk = 0; kk < 4; kk++) {
        uint32_t ah[2][4], al[2][4], bh[8][2], bl[8][2];
        #pragma unroll
        for (int mt = 0; mt < 2; mt++) {
            int m  = warpM * 32 + mt * 16 + (lane & 15);
            int kb = (kk * 16 + (lane >> 4) * 8) * 2;
            int off = m * 128 + kb;
            int sw  = off ^ ((off >> 3) & 0x70);
            ldsm4(ah[mt], Ah + sw);
            ldsm4(al[mt], Al + sw);
        }
        #pragma unroll
        for (int nb2 = 0; nb2 < 4; nb2++) {
            int n  = warpN * 64 + nb2 * 16 + (lane >> 4) * 8 + (lane & 7);
            int kb = (kk * 16 + ((lane >> 3) & 1) * 8) * 2;
            int off = n * 128 + kb;
            int sw  = off ^ ((off >> 3) & 0x70);
            uint32_t r[4];
            ldsm4(r, Bh + sw);
            bh[nb2 * 2][0] = r[0]; bh[nb2 * 2][1] = r[1];
            bh[nb2 * 2 + 1][0] = r[2]; bh[nb2 * 2 + 1][1] = r[3];
            ldsm4(r, Bl + sw);
            bl[nb2 * 2][0] = r[0]; bl[nb2 * 2][1] = r[1];
            bl[nb2 * 2 + 1][0] = r[2]; bl[nb2 * 2 + 1][1] = r[3];
        }
        #pragma unroll
        for (int mt = 0; mt < 2; mt++)
            #pragma unroll
            for (int nb = 0; nb < 8; nb++) {
                mma16816(acc[mt][nb], ah[mt], bh[nb]);
                mma16816(acc[mt][nb], ah[mt], bl[nb]);
                mma16816(acc[mt][nb], al[mt], bh[nb]);
            }
    }
}

__global__ void __launch_bounds__(256, 1)
mma_gemm(const __nv_bfloat16* __restrict__ Wh, const __nv_bfloat16* __restrict__ Wl,
         const __nv_bfloat16* __restrict__ Xh, const __nv_bfloat16* __restrict__ Xl,
         const float* __restrict__ bias,
         float* __restrict__ Y0, float* __restrict__ Y1, float* __restrict__ Y2)
{
    extern __shared__ char smem[];
    const uint32_t sb = smem_u32(smem);
    const int tid = threadIdx.x, wid = tid >> 5, lane = tid & 31;
    const int warpM = wid & 3, warpN = wid >> 2;
    const int n0 = blockIdx.x * 128, m0 = blockIdx.y * 128, b = blockIdx.z;
    const size_t wrow0 = (size_t)m0 * 2048;
    const size_t xrow0 = ((size_t)b * LSEQ + n0) * 2048;
    const char* cWh = (const char*)Wh; const char* cWl = (const char*)Wl;
    const char* cXh = (const char*)Xh; const char* cXl = (const char*)Xl;

    float acc[2][8][4];
    #pragma unroll
    for (int mt = 0; mt < 2; mt++)
        #pragma unroll
        for (int nb = 0; nb < 8; nb++)
            #pragma unroll
            for (int j = 0; j < 4; j++) acc[mt][nb][j] = 0.f;

    g_load_stage(sb,            0, tid, cWh, cWl, cXh, cXl, wrow0, xrow0);
    g_load_stage(sb + GSTG,     1, tid, cWh, cWl, cXh, cXl, wrow0, xrow0);
    g_load_stage(sb + 2 * GSTG, 2, tid, cWh, cWl, cXh, cXl, wrow0, xrow0);

    int slot = 0;
    for (int st = 0; st < 16; st++) {
        if (st <= 13)      asm volatile("cp.async.wait_group 2;" ::: "memory");
        else if (st == 14) asm volatile("cp.async.wait_group 1;" ::: "memory");
        else               asm volatile("cp.async.wait_group 0;" ::: "memory");
        __syncthreads();
        g_compute_stage(sb + slot * GSTG, lane, warpM, warpN, acc);
        __syncthreads();
        if (st + 3 < 16)
            g_load_stage(sb + slot * GSTG, st + 3, tid, cWh, cWl, cXh, cXl, wrow0, xrow0);
        slot = (slot == 2) ? 0 : slot + 1;
    }

    const int mat = m0 >> 10;
    float* Y = (mat == 0) ? Y0 : (mat == 1) ? Y1 : Y2;
    const int rq = lane >> 2;
    const int cq = (lane & 3) * 2;
    #pragma unroll
    for (int mt = 0; mt < 2; mt++) {
        const int rs = m0 + warpM * 32 + mt * 16 + rq;
        const int row = rs & 1023;
        const float b0 = bias[rs], b1 = bias[rs + 8];
        const size_t y0 = ((size_t)b * DM + row) * LSEQ;
        #pragma unroll
        for (int nb = 0; nb < 8; nb++) {
            const int col = n0 + warpN * 64 + nb * 8 + cq;
            float2 v0, v1;
            v0.x = acc[mt][nb][0] + b0; v0.y = acc[mt][nb][1] + b0;
            v1.x = acc[mt][nb][2] + b1; v1.y = acc[mt][nb][3] + b1;
            *(float2*)&Y[y0 + col] = v0;
            *(float2*)&Y[y0 + 8 * LSEQ + col] = v1;
        }
    }
}

// =============================================================================
// Kernel C: per-channel causal long conv + skip.  f32x2, 16 l per thread,
// 2 channels per block.  K row loaded via float4 (broadcast).
// =============================================================================
__global__ void __launch_bounds__(256)
keyconv_kernel(const float* __restrict__ kk, const float* __restrict__ kker,
               const float* __restrict__ dkey, float* __restrict__ out)
{
    extern __shared__ float dsm[];
    float* xp0 = dsm;               // 4608
    float* xp1 = dsm + 4608;        // 4608
    float* ks0 = dsm + 9216;        // 2048
    float* ks1 = dsm + 11264;       // 2048
    const int c0 = blockIdx.x * 2, b = blockIdx.y;
    const int tid = threadIdx.x;
    const size_t rb0 = ((size_t)b * DM + c0) * LSEQ;
    const size_t rb1 = rb0 + LSEQ;

    for (int i = tid; i < 4608; i += 256) { xp0[i] = 0.f; xp1[i] = 0.f; }
    __syncthreads();
    for (int i = tid; i < 2048; i += 256) {
        ks0[i] = kker[(size_t)c0 * LSEQ + i];
        ks1[i] = kker[(size_t)(c0 + 1) * LSEQ + i];
        int p = 2048 + i;
        int a = p + (p >> 4);
        xp0[a] = kk[rb0 + i];
        xp1[a] = kk[rb1 + i];
    }
    __syncthreads();

    const int wid = tid >> 5, lane = tid & 31;
    const int ch = (wid < 4) ? 0 : 1;
    const int strip = (wid < 4) ? wid : (7 - wid);
    float* X = ch ? xp1 : xp0;
    float* K = ch ? ks1 : ks0;
    const int c = c0 + ch;
    const size_t rowbase = ch ? rb1 : rb0;
    const int l0 = strip * 512 + lane * 16;
    const int jmax = strip * 512 + 511;

    ull acc2[8];
    #pragma unroll
    for (int r2 = 0; r2 < 8; r2++) acc2[r2] = 0ull;

    for (int j0 = 0; j0 <= jmax; j0 += 8) {
        float4 kA = *(const float4*)&K[j0];
        float4 kB = *(const float4*)&K[j0 + 4];
        ull kr2[8];
        kr2[0] = pk2(kA.x, kA.x); kr2[1] = pk2(kA.y, kA.y);
        kr2[2] = pk2(kA.z, kA.z); kr2[3] = pk2(kA.w, kA.w);
        kr2[4] = pk2(kB.x, kB.x); kr2[5] = pk2(kB.y, kB.y);
        kr2[6] = pk2(kB.z, kB.z); kr2[7] = pk2(kB.w, kB.w);
        float xv[23];
        #pragma unroll
        for (int t = 0; t < 23; t++) {
            int p = 2048 + l0 - j0 - 7 + t;
            xv[t] = X[p + (p >> 4)];
        }
        ull xv2[22];
        #pragma unroll
        for (int t = 0; t < 22; t++) xv2[t] = pk2(xv[t], xv[t + 1]);
        #pragma unroll
        for (int r2 = 0; r2 < 8; r2++)
            #pragma unroll
            for (int s = 0; s < 8; s++)
                acc2[r2] = fma2(kr2[s], xv2[2 * r2 - s + 7], acc2[r2]);
    }
    const float dk = dkey[c];
    #pragma unroll
    for (int r2 = 0; r2 < 8; r2++) {
        float a0, a1;
        upk2(acc2[r2], a0, a1);
        int p0 = 2048 + l0 + 2 * r2;
        int p1 = p0 + 1;
        out[rowbase + l0 + 2 * r2]     = a0 + X[p0 + (p0 >> 4)] * dk;
        out[rowbase + l0 + 2 * r2 + 1] = a1 + X[p1 + (p1 >> 4)] * dk;
    }
}

// =============================================================================
// Kernel D: kernel-weighted linear attention — f32x2, m-chunk 4:
// k/v via float4 broadcast loads, kp via 11-wide sliding register window.
// Arithmetic order identical to R6 (bitwise-same result).
// =============================================================================
__global__ void __launch_bounds__(256)
attn_kernel(const float* __restrict__ gq, const float* __restrict__ gk,
            const float* __restrict__ gv, const float* __restrict__ kerv,
            const float* __restrict__ Dp, float* __restrict__ gy)
{
    extern __shared__ float sm[];
    float* ks = sm;
    float* vs = sm + 8192;
    float* kp = sm + 16384;
    const int h = blockIdx.x, b = blockIdx.y;
    const int tid = threadIdx.x;
    const size_t base = ((size_t)b * DM + (size_t)h * HD) * LSEQ;

    for (int i = tid; i < 8192; i += 256) { ks[i] = gk[base + i]; vs[i] = gv[base + i]; }
    for (int i = tid; i < 4608; i += 256) kp[i] = 0.f;
    __syncthreads();
    for (int j = tid; j < 2048; j += 256) {
        int p = 2048 + j;
        kp[p + (p >> 3)] = kerv[(size_t)h * LSEQ + j];
    }
    __syncthreads();

    const int wid = tid >> 5, lane = tid & 31;
    const int strip = (wid < 4) ? wid : (11 - wid);
    const int l0 = strip * 256 + lane * 8;
    const int mmax = strip * 256 + 255;

    ull q2[4][4];
    #pragma unroll
    for (int d1 = 0; d1 < 4; d1++)
        #pragma unroll
        for (int r2 = 0; r2 < 4; r2++) {
            float2 qq = *(const float2*)&gq[base + (size_t)d1 * LSEQ + l0 + 2 * r2];
            q2[d1][r2] = pk2(qq.x, qq.y);
        }

    ull acc2[4][4];
    #pragma unroll
    for (int d = 0; d < 4; d++)
        #pragma unroll
        for (int r2 = 0; r2 < 4; r2++) acc2[d][r2] = 0ull;

    const int pb = 2048 + l0;

    for (int mb = 0; mb <= mmax; mb += 4) {
        // k/v rows, 4 consecutive m per row, one LDS.128 each (broadcast)
        float4 kf0 = *(const float4*)&ks[mb];
        float4 kf1 = *(const float4*)&ks[2048 + mb];
        float4 kf2 = *(const float4*)&ks[4096 + mb];
        float4 kf3 = *(const float4*)&ks[6144 + mb];
        float4 vf0 = *(const float4*)&vs[mb];
        float4 vf1 = *(const float4*)&vs[2048 + mb];
        float4 vf2 = *(const float4*)&vs[4096 + mb];
        float4 vf3 = *(const float4*)&vs[6144 + mb];
        float ka[4][4] = {{kf0.x,kf0.y,kf0.z,kf0.w},{kf1.x,kf1.y,kf1.z,kf1.w},
                          {kf2.x,kf2.y,kf2.z,kf2.w},{kf3.x,kf3.y,kf3.z,kf3.w}};
        float va[4][4] = {{vf0.x,vf0.y,vf0.z,vf0.w},{vf1.x,vf1.y,vf1.z,vf1.w},
                          {vf2.x,vf2.y,vf2.z,vf2.w},{vf3.x,vf3.y,vf3.z,vf3.w}};
        // kp window: covers p = pb + 2*r2 - (mb+i) .. +1 for r2 0..3, i 0..3
        float w11[11];
        #pragma unroll
        for (int t = 0; t < 11; t++) {
            int p = pb - mb - 3 + t;
            w11[t] = kp[p + (p >> 3)];
        }
        #pragma unroll
        for (int i = 0; i < 4; i++) {
            ull kk0 = pk2(ka[0][i], ka[0][i]), kk1 = pk2(ka[1][i], ka[1][i]);
            ull kk2 = pk2(ka[2][i], ka[2][i]), kk3 = pk2(ka[3][i], ka[3][i]);
            ull vv0 = pk2(va[0][i], va[0][i]), vv1 = pk2(va[1][i], va[1][i]);
            ull vv2 = pk2(va[2][i], va[2][i]), vv3 = pk2(va[3][i], va[3][i]);
            #pragma unroll
            for (int r2 = 0; r2 < 4; r2++) {
                ull s = mul2(q2[0][r2], kk0);
                s = fma2(q2[1][r2], kk1, s);
                s = fma2(q2[2][r2], kk2, s);
                s = fma2(q2[3][r2], kk3, s);
                ull kerp = pk2(w11[2 * r2 - i + 3], w11[2 * r2 - i + 4]);
                ull w = mul2(s, kerp);
                acc2[0][r2] = fma2(w, vv0, acc2[0][r2]);
                acc2[1][r2] = fma2(w, vv1, acc2[1][r2]);
                acc2[2][r2] = fma2(w, vv2, acc2[2][r2]);
                acc2[3][r2] = fma2(w, vv3, acc2[3][r2]);
            }
        }
    }

    float acc[4][8];
    #pragma unroll
    for (int d = 0; d < 4; d++)
        #pragma unroll
        for (int r2 = 0; r2 < 4; r2++)
            upk2(acc2[d][r2], acc[d][2 * r2], acc[d][2 * r2 + 1]);

    const float Dh = Dp[h];
    float qreg[4][8];
    #pragma unroll
    for (int d1 = 0; d1 < 4; d1++)
        #pragma unroll
        for (int r2 = 0; r2 < 4; r2++)
            upk2(q2[d1][r2], qreg[d1][2 * r2], qreg[d1][2 * r2 + 1]);
    #pragma unroll
    for (int r = 0; r < 8; r++) {
        int l = l0 + r;
        float s = qreg[0][r] * ks[l] + qreg[1][r] * ks[2048 + l]
                + qreg[2][r] * ks[4096 + l] + qreg[3][r] * ks[6144 + l];
        float w = Dh * s;
        acc[0][r] += w * vs[l];
        acc[1][r] += w * vs[2048 + l];
        acc[2][r] += w * vs[4096 + l];
        acc[3][r] += w * vs[6144 + l];
    }

    #pragma unroll
    for (int d2 = 0; d2 < 4; d2++) {
        size_t orow = ((size_t)b * DM + (size_t)d2 * HH + h) * LSEQ + l0;
        #pragma unroll
        for (int r = 0; r < 8; r++) {
            float x = acc[d2][r];
            gy[orow + r] = 0.5f * x * (1.f + erff(x * 0.70710678118654752f));
        }
    }
}

// =============================================================================
extern "C" void kernel_launch(void* const* d_in, const int* in_sizes, int n_in,
                              void* d_out, int out_size)
{
    const float* u       = (const float*)d_in[0];
    const float* q_w     = (const float*)d_in[1];
    const float* q_b     = (const float*)d_in[2];
    const float* k_w     = (const float*)d_in[3];
    const float* k_b     = (const float*)d_in[4];
    const float* v_w     = (const float*)d_in[5];
    const float* v_b     = (const float*)d_in[6];
    const float* kkey_in = (const float*)d_in[7];
    const float* kv_in   = (const float*)d_in[8];
    const float* D_key   = (const float*)d_in[9];
    const float* Dh      = (const float*)d_in[10];
    const float* pw_w    = (const float*)d_in[11];
    const float* pw_b    = (const float*)d_in[12];
    float* out = (float*)d_out;

    float *kkey, *kvk, *q, *k, *v, *kc, *y, *bias;
    __nv_bfloat16 *wh, *wl, *xh, *xl;
    cudaGetSymbolAddress((void**)&kkey, g_kkey);
    cudaGetSymbolAddress((void**)&kvk,  g_kvker);
    cudaGetSymbolAddress((void**)&q,    g_q);
    cudaGetSymbolAddress((void**)&k,    g_k);
    cudaGetSymbolAddress((void**)&v,    g_v);
    cudaGetSymbolAddress((void**)&kc,   g_kc);
    cudaGetSymbolAddress((void**)&y,    g_y);
    cudaGetSymbolAddress((void**)&bias, g_bias);
    cudaGetSymbolAddress((void**)&wh,   g_wh);
    cudaGetSymbolAddress((void**)&wl,   g_wl);
    cudaGetSymbolAddress((void**)&xh,   g_xh);
    cudaGetSymbolAddress((void**)&xl,   g_xl);

    const int ATT_SMEM = (8192 + 8192 + 4608) * (int)sizeof(float);   // 83968
    const int KC_SMEM  = (2 * 4608 + 2 * 2048) * (int)sizeof(float);  // 53248
    cudaFuncSetAttribute(attn_kernel, cudaFuncAttributeMaxDynamicSharedMemorySize, ATT_SMEM);
    cudaFuncSetAttribute(keyconv_kernel, cudaFuncAttributeMaxDynamicSharedMemorySize, KC_SMEM);
    cudaFuncSetAttribute(mma_gemm, cudaFuncAttributeMaxDynamicSharedMemorySize, 3 * GSTG);

    // 1. build conv kernels (merged launch)
    build_kernels<<<DM + HH, 256>>>(kkey_in, kv_in, kkey, kvk);

    // 2. split weights to bf16 hi/lo (merged) + pack qkv biases
    wsplit4<<<dim3(DM * DM / 256, 4), 256>>>(q_w, k_w, v_w, pw_w, wh, wl);
    pack_bias<<<3 * DM / 256, 256>>>(q_b, k_b, v_b, bias);

    // 3. transpose + split u -> (b, l, c) bf16
    trans_split<<<dim3(LSEQ / 32, DM / 32, BB), 256>>>(u, xh, xl);

    // 4. merged q/k/v projection (stacked M = 3072)
    mma_gemm<<<dim3(LSEQ / 128, 3 * DM / 128, BB), 256, 3 * GSTG>>>(
        wh, wl, xh, xl, bias, q, k, v);

    // 5. key-side causal long conv + skip
    keyconv_kernel<<<dim3(DM / 2, BB), 256, KC_SMEM>>>(k, kkey, D_key, kc);

    // 6. kernel-weighted linear attention + D skip + gelu
    attn_kernel<<<dim3(HH, BB), 256, ATT_SMEM>>>(q, kc, v, kvk, Dh, y);

    // 7. transpose + split y, pointwise projection -> out
    trans_split<<<dim3(LSEQ / 32, DM / 32, BB), 256>>>(y, xh, xl);
    mma_gemm<<<dim3(LSEQ / 128, DM / 128, BB), 256, 3 * GSTG>>>(
        wh + 3 * (size_t)(DM * DM), wl + 3 * (size_t)(DM * DM), xh, xl, pw_b, out, out, out);
}